// round 5
// baseline (speedup 1.0000x reference)
#include <cuda_runtime.h>
#include <cstdint>
#include <math.h>

typedef unsigned long long ull;

#define C_CAND 32768
#define HID    1024
#define K4     4096
#define NREL   10

// ---- scratch (static device globals; no allocations anywhere) ----
__device__ float g_feats[(size_t)C_CAND * K4];   // 512 MB
__device__ float g_h[(size_t)C_CAND * HID];      // 128 MB
__device__ float g_loss[C_CAND];
__device__ float g_logits_sink[(size_t)C_CAND * NREL]; // fallback sink if d_out has no logits slot

// ---- packed f32x2 helpers (Blackwell FFMA2 path) ----
__device__ __forceinline__ ull dup_f32(float a) {
    ull d;
    unsigned int r = __float_as_uint(a);
    asm("mov.b64 %0, {%1, %1};" : "=l"(d) : "r"(r));
    return d;
}
__device__ __forceinline__ void ffma2(ull& acc, ull a, ull b) {
    asm("fma.rn.f32x2 %0, %1, %2, %0;" : "+l"(acc) : "l"(a), "l"(b));
}
union F2U { ull u; float2 f; };

__device__ __forceinline__ float gelu_exact(float x) {
    return 0.5f * x * (1.0f + erff(x * 0.70710678118654752440f));
}

// ============================================================================
// Kernel 1: gather + build feats = [src, dst, |src-dst|, src*dst]   [C, 4H]
// One block per candidate, 256 threads, one float4 per thread per quarter.
// ============================================================================
__global__ void build_feats_kernel(const float* __restrict__ emb,
                                   const int* __restrict__ src_idx,
                                   const int* __restrict__ dst_idx) {
    const int c = blockIdx.x;
    const int h = threadIdx.x << 2;                 // 0..1020
    const int si = src_idx[c];
    const int di = dst_idx[c];

    const float4 s = *(const float4*)(emb + (size_t)si * HID + h);
    const float4 d = *(const float4*)(emb + (size_t)di * HID + h);

    float4 ad, pd;
    ad.x = fabsf(s.x - d.x); ad.y = fabsf(s.y - d.y);
    ad.z = fabsf(s.z - d.z); ad.w = fabsf(s.w - d.w);
    pd.x = s.x * d.x; pd.y = s.y * d.y; pd.z = s.z * d.z; pd.w = s.w * d.w;

    float* fb = g_feats + (size_t)c * K4;
    *(float4*)(fb + h)            = s;
    *(float4*)(fb + HID + h)      = d;
    *(float4*)(fb + 2 * HID + h)  = ad;
    *(float4*)(fb + 3 * HID + h)  = pd;
}

// ============================================================================
// Kernel 2: h = gelu(feats @ W1 + b1)     M=32768, N=1024, K=4096
// 128x128x8 block tile, 256 threads, 16(M)x4(N) per-thread tile.
// M-pairs come free from 128-bit LDS -> aligned reg pairs for FFMA2;
// only the 4 N-scalars are duplicated per k-step.
// ============================================================================
__global__ __launch_bounds__(256, 2)
void gemm1_kernel(const float* __restrict__ W1, const float* __restrict__ b1) {
    __shared__ __align__(16) float As[8][128];   // [k][m]
    __shared__ __align__(16) float Bs[8][128];   // [k][n]

    const int tid = threadIdx.x;
    const int bx = blockIdx.x;      // N tile (0..7)
    const int by = blockIdx.y;      // M tile (0..255)
    const int tx = tid & 31;        // N thread (0..31) -> 4 cols
    const int ty = tid >> 5;        // M thread (0..7)  -> 16 rows

    // loaders
    const int a_row = tid >> 1;             // 0..127
    const int a_col = (tid & 1) << 2;       // 0 or 4
    const int b_row = tid >> 5;             // 0..7
    const int b_col = (tid & 31) << 2;      // 0..124

    const float* Ap = g_feats + (size_t)(by * 128 + a_row) * K4 + a_col;
    const float* Bp = W1 + (size_t)b_row * HID + bx * 128 + b_col;

    ull acc[8][4];
    #pragma unroll
    for (int m = 0; m < 8; ++m)
        #pragma unroll
        for (int n = 0; n < 4; ++n) acc[m][n] = 0ULL;   // (0.0f, 0.0f)

    float4 a_ld = *(const float4*)Ap;
    float4 b_ld = *(const float4*)Bp;

    const int NT = K4 / 8;   // 512
    for (int t = 0; t < NT; ++t) {
        As[a_col + 0][a_row] = a_ld.x;
        As[a_col + 1][a_row] = a_ld.y;
        As[a_col + 2][a_row] = a_ld.z;
        As[a_col + 3][a_row] = a_ld.w;
        *(float4*)&Bs[b_row][b_col] = b_ld;
        __syncthreads();

        if (t + 1 < NT) {
            a_ld = *(const float4*)(Ap + (t + 1) * 8);
            b_ld = *(const float4*)(Bp + (size_t)(t + 1) * 8 * HID);
        }

        #pragma unroll
        for (int kk = 0; kk < 8; ++kk) {
            const ulonglong2* ap2 = (const ulonglong2*)&As[kk][ty * 16];
            ulonglong2 v0 = ap2[0], v1 = ap2[1], v2 = ap2[2], v3 = ap2[3];
            ull av[8] = { v0.x, v0.y, v1.x, v1.y, v2.x, v2.y, v3.x, v3.y };

            float4 bv = *(const float4*)&Bs[kk][tx * 4];
            ull bd0 = dup_f32(bv.x);
            ull bd1 = dup_f32(bv.y);
            ull bd2 = dup_f32(bv.z);
            ull bd3 = dup_f32(bv.w);

            #pragma unroll
            for (int m = 0; m < 8; ++m) {
                ffma2(acc[m][0], av[m], bd0);
                ffma2(acc[m][1], av[m], bd1);
                ffma2(acc[m][2], av[m], bd2);
                ffma2(acc[m][3], av[m], bd3);
            }
        }
        __syncthreads();
    }

    // epilogue: + bias, exact GELU, store h
    const int row0 = by * 128 + ty * 16;
    const int col0 = bx * 128 + tx * 4;
    float bias[4];
    #pragma unroll
    for (int n = 0; n < 4; ++n) bias[n] = b1[col0 + n];

    #pragma unroll
    for (int m = 0; m < 8; ++m) {
        const size_t r0 = (size_t)(row0 + 2 * m) * HID;
        const size_t r1 = (size_t)(row0 + 2 * m + 1) * HID;
        #pragma unroll
        for (int n = 0; n < 4; ++n) {
            F2U u; u.u = acc[m][n];
            const int col = col0 + n;
            g_h[r0 + col] = gelu_exact(u.f.x + bias[n]);
            g_h[r1 + col] = gelu_exact(u.f.y + bias[n]);
        }
    }
}

// ============================================================================
// Kernel 3: logits = h @ W2 + b2 ; log-softmax ; per-candidate NLL
// One warp per candidate. W2 transposed into smem ([r][k]) -> conflict-free.
// ============================================================================
__global__ __launch_bounds__(256)
void head_kernel(const float* __restrict__ W2, const float* __restrict__ b2,
                 const int* __restrict__ labels, float* __restrict__ logits_out) {
    __shared__ float Wt[NREL][HID];   // 40 KB

    const int tid = threadIdx.x;
    for (int i = tid; i < NREL * HID; i += 256) {
        const int k = i / NREL;
        const int r = i - k * NREL;
        Wt[r][k] = W2[i];
    }
    __syncthreads();

    const int warp = tid >> 5;
    const int lane = tid & 31;
    const int c = blockIdx.x * 8 + warp;

    const float* hrow = g_h + (size_t)c * HID;
    float acc[NREL];
    #pragma unroll
    for (int r = 0; r < NREL; ++r) acc[r] = 0.0f;

    #pragma unroll 4
    for (int i = 0; i < 32; ++i) {
        const int k = i * 32 + lane;
        const float hv = hrow[k];
        #pragma unroll
        for (int r = 0; r < NREL; ++r) acc[r] += hv * Wt[r][k];
    }

    // deterministic warp tree reduction
    #pragma unroll
    for (int r = 0; r < NREL; ++r) {
        #pragma unroll
        for (int off = 16; off > 0; off >>= 1)
            acc[r] += __shfl_down_sync(0xffffffffu, acc[r], off);
    }

    if (lane == 0) {
        float lg[NREL];
        float mx = -1e30f;
        #pragma unroll
        for (int r = 0; r < NREL; ++r) {
            lg[r] = acc[r] + b2[r];
            mx = fmaxf(mx, lg[r]);
        }
        float s = 0.0f;
        #pragma unroll
        for (int r = 0; r < NREL; ++r) s += expf(lg[r] - mx);
        const float lse = logf(s) + mx;

        const int lbl = labels[c];
        g_loss[c] = lse - lg[lbl];

        float* dst = logits_out + (size_t)c * NREL;
        #pragma unroll
        for (int r = 0; r < NREL; ++r) dst[r] = lg[r];
    }
}

// ============================================================================
// Kernel 4: loss = mean(g_loss)  -- single block, fixed-order tree (deterministic)
// ============================================================================
__global__ void reduce_loss_kernel(float* __restrict__ loss_out) {
    __shared__ float sm[1024];
    const int tid = threadIdx.x;
    float s = 0.0f;
    #pragma unroll
    for (int i = 0; i < 32; ++i) s += g_loss[tid + (i << 10)];
    sm[tid] = s;
    __syncthreads();
    for (int off = 512; off > 0; off >>= 1) {
        if (tid < off) sm[tid] += sm[tid + off];
        __syncthreads();
    }
    if (tid == 0) loss_out[0] = sm[0] * (1.0f / (float)C_CAND);
}

// ============================================================================
// launch
// ============================================================================
extern "C" void kernel_launch(void* const* d_in, const int* in_sizes, int n_in,
                              void* d_out, int out_size) {
    const float* emb    = (const float*)d_in[0];   // [100000, 1024]
    const int*   src    = (const int*)d_in[1];     // [32768]
    const int*   dst    = (const int*)d_in[2];     // [32768]
    const int*   labels = (const int*)d_in[3];     // [32768]
    const float* W1     = (const float*)d_in[4];   // [4096, 1024]
    const float* b1     = (const float*)d_in[5];   // [1024]
    const float* W2     = (const float*)d_in[6];   // [1024, 10]
    const float* b2     = (const float*)d_in[7];   // [10]

    float* out = (float*)d_out;
    float* logits_dst;
    float* loss_dst = nullptr;

    if (out_size >= C_CAND * NREL + 1) {
        // tuple (loss, logits) flattened in return order
        loss_dst   = out;
        logits_dst = out + 1;
    } else if (out_size == C_CAND * NREL) {
        logits_dst = out;               // logits only
    } else {
        // loss only: logits go to a device-global sink
        void* p = nullptr;
        cudaGetSymbolAddress(&p, g_logits_sink);
        logits_dst = (float*)p;
        loss_dst   = out;
    }

    build_feats_kernel<<<C_CAND, 256>>>(emb, src, dst);

    dim3 g2(HID / 128, C_CAND / 128);   // (8, 256) — x over N first => A tiles reused in L2
    gemm1_kernel<<<g2, 256>>>(W1, b1);

    head_kernel<<<C_CAND / 8, 256>>>(W2, b2, labels, logits_dst);

    if (loss_dst) reduce_loss_kernel<<<1, 1024>>>(loss_dst);
}

// round 8
// speedup vs baseline: 2.2231x; 2.2231x over previous
#include <cuda_runtime.h>
#include <cuda_bf16.h>
#include <cstdint>
#include <math.h>

typedef unsigned long long ull;

#define C_CAND 32768
#define HID    1024
#define K4     4096
#define NREL   10

// ---- scratch (static device globals; no allocations anywhere) ----
__device__ __align__(16) __nv_bfloat16 g_fHi[(size_t)C_CAND * K4];   // 256 MB feats hi
__device__ __align__(16) __nv_bfloat16 g_fLo[(size_t)C_CAND * K4];   // 256 MB feats lo
__device__ __align__(16) __nv_bfloat16 g_wHi[(size_t)HID * K4];      // 8 MB  W1^T hi [n][k]
__device__ __align__(16) __nv_bfloat16 g_wLo[(size_t)HID * K4];      // 8 MB  W1^T lo
__device__ __align__(16) float g_h[(size_t)C_CAND * HID];            // 128 MB
__device__ float g_loss[C_CAND];
__device__ float g_logits_sink[(size_t)C_CAND * NREL];

__device__ __forceinline__ float gelu_exact(float x) {
    return 0.5f * x * (1.0f + erff(x * 0.70710678118654752440f));
}

// ============================ PTX helpers (sm_80+ base-target only) =========
__device__ __forceinline__ uint32_t smem_u32(const void* p) {
    uint32_t a;
    asm("{ .reg .u64 t; cvta.to.shared.u64 t, %1; cvt.u32.u64 %0, t; }" : "=r"(a) : "l"(p));
    return a;
}
__device__ __forceinline__ void cpasync16(uint32_t dst, const void* src) {
    asm volatile("cp.async.cg.shared.global [%0], [%1], 16;" :: "r"(dst), "l"(src));
}
__device__ __forceinline__ void ldsm4(uint32_t& r0, uint32_t& r1, uint32_t& r2,
                                      uint32_t& r3, uint32_t addr) {
    asm volatile("ldmatrix.sync.aligned.m8n8.x4.shared.b16 {%0,%1,%2,%3}, [%4];"
                 : "=r"(r0), "=r"(r1), "=r"(r2), "=r"(r3) : "r"(addr));
}
__device__ __forceinline__ void mma16816(float* c, const uint32_t* a, const uint32_t* b) {
    asm volatile(
        "mma.sync.aligned.m16n8k16.row.col.f32.bf16.bf16.f32 "
        "{%0,%1,%2,%3}, {%4,%5,%6,%7}, {%8,%9}, {%0,%1,%2,%3};"
        : "+f"(c[0]), "+f"(c[1]), "+f"(c[2]), "+f"(c[3])
        : "r"(a[0]), "r"(a[1]), "r"(a[2]), "r"(a[3]), "r"(b[0]), "r"(b[1]));
}

// ============================================================================
// Kernel 0: transpose + bf16-split W1 -> g_wHi/g_wLo as [N=1024][K=4096]
// ============================================================================
__global__ void wsplit_kernel(const float* __restrict__ W1) {
    __shared__ float sm[32][33];
    const int k0 = blockIdx.x * 32;
    const int n0 = blockIdx.y * 32;
    const int tx = threadIdx.x, ty = threadIdx.y;   // 32 x 8
    #pragma unroll
    for (int i = 0; i < 4; ++i)
        sm[ty + i * 8][tx] = W1[(size_t)(k0 + ty + i * 8) * HID + n0 + tx];
    __syncthreads();
    #pragma unroll
    for (int i = 0; i < 4; ++i) {
        const int n = ty + i * 8;
        const float v = sm[tx][n];                  // = W1[k0+tx][n0+n]
        const __nv_bfloat16 hb = __float2bfloat16_rn(v);
        const float lo = v - __bfloat162float(hb);
        const size_t o = (size_t)(n0 + n) * K4 + k0 + tx;
        g_wHi[o] = hb;
        g_wLo[o] = __float2bfloat16_rn(lo);
    }
}

// ============================================================================
// Kernel 1: gather + build feats, split to bf16 hi/lo   [C, 4H]
// ============================================================================
__device__ __forceinline__ void split_store4(float4 v, size_t elem_off) {
    unsigned short h0 = __bfloat16_as_ushort(__float2bfloat16_rn(v.x));
    unsigned short h1 = __bfloat16_as_ushort(__float2bfloat16_rn(v.y));
    unsigned short h2 = __bfloat16_as_ushort(__float2bfloat16_rn(v.z));
    unsigned short h3 = __bfloat16_as_ushort(__float2bfloat16_rn(v.w));
    float r0 = v.x - __bfloat162float(__ushort_as_bfloat16(h0));
    float r1 = v.y - __bfloat162float(__ushort_as_bfloat16(h1));
    float r2 = v.z - __bfloat162float(__ushort_as_bfloat16(h2));
    float r3 = v.w - __bfloat162float(__ushort_as_bfloat16(h3));
    unsigned short l0 = __bfloat16_as_ushort(__float2bfloat16_rn(r0));
    unsigned short l1 = __bfloat16_as_ushort(__float2bfloat16_rn(r1));
    unsigned short l2 = __bfloat16_as_ushort(__float2bfloat16_rn(r2));
    unsigned short l3 = __bfloat16_as_ushort(__float2bfloat16_rn(r3));
    uint2 hi, lo;
    hi.x = (uint32_t)h0 | ((uint32_t)h1 << 16);
    hi.y = (uint32_t)h2 | ((uint32_t)h3 << 16);
    lo.x = (uint32_t)l0 | ((uint32_t)l1 << 16);
    lo.y = (uint32_t)l2 | ((uint32_t)l3 << 16);
    *(uint2*)(g_fHi + elem_off) = hi;
    *(uint2*)(g_fLo + elem_off) = lo;
}

__global__ void build_feats_kernel(const float* __restrict__ emb,
                                   const int* __restrict__ src_idx,
                                   const int* __restrict__ dst_idx) {
    const int c = blockIdx.x;
    const int h = threadIdx.x << 2;                 // 0..1020
    const int si = src_idx[c];
    const int di = dst_idx[c];

    const float4 s = *(const float4*)(emb + (size_t)si * HID + h);
    const float4 d = *(const float4*)(emb + (size_t)di * HID + h);

    float4 ad, pd;
    ad.x = fabsf(s.x - d.x); ad.y = fabsf(s.y - d.y);
    ad.z = fabsf(s.z - d.z); ad.w = fabsf(s.w - d.w);
    pd.x = s.x * d.x; pd.y = s.y * d.y; pd.z = s.z * d.z; pd.w = s.w * d.w;

    const size_t base = (size_t)c * K4;
    split_store4(s,  base + h);
    split_store4(d,  base + HID + h);
    split_store4(ad, base + 2 * HID + h);
    split_store4(pd, base + 3 * HID + h);
}

// ============================================================================
// Kernel 2: h = gelu(feats @ W1 + b1) via mma.sync bf16 3-product emulation
// CTA tile 128x128, Kc=64 (128B smem rows, SW128 xor swizzle), 3-stage
// cp.async pipeline. 8 warps in 4(M)x2(N), warp tile 32x64.
// Per k16: 12 ldmatrix.x4, 48 HMMA (AhiBhi + AhiBlo + AloBhi).
// ============================================================================
#define BK          64
#define NSTAGE      3
#define STG_BYTES   65536    // Ahi 16K | Alo 16K | Bhi 16K | Blo 16K
#define OFF_AHI     0
#define OFF_ALO     16384
#define OFF_BHI     32768
#define OFF_BLO     49152
#define GEMM_SMEM   (NSTAGE * STG_BYTES)

__device__ __forceinline__ void load_stage(int t, int slot, int tid, int m0, int n0,
                                           uint32_t sb) {
    const int k0 = t * BK;
    const uint32_t st = sb + slot * STG_BYTES;
    #pragma unroll
    for (int i = 0; i < 4; ++i) {
        const int idx = i * 256 + tid;         // 0..1023
        const int r = idx >> 3;                // row 0..127
        const int c = idx & 7;                 // 16B chunk 0..7
        const uint32_t d = st + r * 128 + ((c ^ (r & 7)) << 4);
        const size_t goA = (size_t)(m0 + r) * K4 + k0 + c * 8;
        const size_t goB = (size_t)(n0 + r) * K4 + k0 + c * 8;
        cpasync16(d + OFF_AHI, g_fHi + goA);
        cpasync16(d + OFF_ALO, g_fLo + goA);
        cpasync16(d + OFF_BHI, g_wHi + goB);
        cpasync16(d + OFF_BLO, g_wLo + goB);
    }
}

__global__ void __launch_bounds__(256, 1)
gemm1_mma_kernel(const float* __restrict__ b1) {
    extern __shared__ __align__(128) char smem[];
    const uint32_t sb = smem_u32(smem);
    const int tid  = threadIdx.x;
    const int lane = tid & 31;
    const int wrp  = tid >> 5;
    const int n0 = blockIdx.x * 128;     // x fastest: N tiles of one M block co-run
    const int m0 = blockIdx.y * 128;

    const int m_off = (wrp & 3) * 32;    // warp M origin within CTA tile
    const int n_off = (wrp >> 2) * 64;   // warp N origin

    // ldmatrix lane addressing (row = base + (lane&15), chunk ^= lane&7)
    const int l15 = lane & 15;
    const int lhf = lane >> 4;
    const int l7  = lane & 7;
    uint32_t rowA[2], rowB[4], swk[4];
    #pragma unroll
    for (int mt = 0; mt < 2; ++mt) rowA[mt] = (uint32_t)(m_off + mt * 16 + l15) * 128;
    #pragma unroll
    for (int nt = 0; nt < 4; ++nt) rowB[nt] = (uint32_t)(n_off + nt * 16 + l15) * 128;
    #pragma unroll
    for (int kk = 0; kk < 4; ++kk) swk[kk] = (uint32_t)(((2 * kk + lhf) ^ l7) << 4);

    float acc[2][8][4];
    #pragma unroll
    for (int mt = 0; mt < 2; ++mt)
        #pragma unroll
        for (int j = 0; j < 8; ++j)
            #pragma unroll
            for (int q = 0; q < 4; ++q) acc[mt][j][q] = 0.0f;

    load_stage(0, 0, tid, m0, n0, sb);
    asm volatile("cp.async.commit_group;" ::: "memory");
    load_stage(1, 1, tid, m0, n0, sb);
    asm volatile("cp.async.commit_group;" ::: "memory");

    const int NT = K4 / BK;   // 64
    int slot = 0;
    for (int t = 0; t < NT; ++t) {
        asm volatile("cp.async.wait_group 1;" ::: "memory");
        __syncthreads();

        // prefetch t+2 into the slot freed at iter t-1
        if (t + 2 < NT) {
            int ns = slot + 2; if (ns >= NSTAGE) ns -= NSTAGE;
            load_stage(t + 2, ns, tid, m0, n0, sb);
        }
        asm volatile("cp.async.commit_group;" ::: "memory");

        const uint32_t st = sb + slot * STG_BYTES;
        #pragma unroll
        for (int kk = 0; kk < 4; ++kk) {
            uint32_t aH[2][4], aL[2][4];
            #pragma unroll
            for (int mt = 0; mt < 2; ++mt) {
                ldsm4(aH[mt][0], aH[mt][1], aH[mt][2], aH[mt][3],
                      st + OFF_AHI + rowA[mt] + swk[kk]);
                ldsm4(aL[mt][0], aL[mt][1], aL[mt][2], aL[mt][3],
                      st + OFF_ALO + rowA[mt] + swk[kk]);
            }
            uint32_t bH[8][2], bL[8][2];
            #pragma unroll
            for (int nt = 0; nt < 4; ++nt) {
                uint32_t r0, r1, r2, r3;
                ldsm4(r0, r1, r2, r3, st + OFF_BHI + rowB[nt] + swk[kk]);
                bH[2 * nt][0] = r0; bH[2 * nt][1] = r2;
                bH[2 * nt + 1][0] = r1; bH[2 * nt + 1][1] = r3;
                ldsm4(r0, r1, r2, r3, st + OFF_BLO + rowB[nt] + swk[kk]);
                bL[2 * nt][0] = r0; bL[2 * nt][1] = r2;
                bL[2 * nt + 1][0] = r1; bL[2 * nt + 1][1] = r3;
            }
            #pragma unroll
            for (int mt = 0; mt < 2; ++mt)
                #pragma unroll
                for (int j = 0; j < 8; ++j) {
                    mma16816(acc[mt][j], aH[mt], bH[j]);
                    mma16816(acc[mt][j], aH[mt], bL[j]);
                    mma16816(acc[mt][j], aL[mt], bH[j]);
                }
        }
        __syncthreads();
        ++slot; if (slot >= NSTAGE) slot = 0;
    }

    // epilogue: + bias, exact GELU, direct global stores (float2)
    const int mrow = m0 + m_off + (lane >> 2);
    const int col0 = n0 + n_off + 2 * (lane & 3);
    #pragma unroll
    for (int mt = 0; mt < 2; ++mt) {
        const int r = mrow + mt * 16;
        #pragma unroll
        for (int j = 0; j < 8; ++j) {
            const int c = col0 + j * 8;
            const float bb0 = __ldg(b1 + c);
            const float bb1 = __ldg(b1 + c + 1);
            float2 v0, v1;
            v0.x = gelu_exact(acc[mt][j][0] + bb0);
            v0.y = gelu_exact(acc[mt][j][1] + bb1);
            v1.x = gelu_exact(acc[mt][j][2] + bb0);
            v1.y = gelu_exact(acc[mt][j][3] + bb1);
            *(float2*)(g_h + (size_t)r * HID + c)       = v0;
            *(float2*)(g_h + (size_t)(r + 8) * HID + c) = v1;
        }
    }
}

// ============================================================================
// Kernel 3: logits = h @ W2 + b2 ; log-softmax ; per-candidate NLL
// ============================================================================
__global__ __launch_bounds__(256)
void head_kernel(const float* __restrict__ W2, const float* __restrict__ b2,
                 const int* __restrict__ labels, float* __restrict__ logits_out) {
    __shared__ float Wt[NREL][HID];   // 40 KB

    const int tid = threadIdx.x;
    for (int i = tid; i < NREL * HID; i += 256) {
        const int k = i / NREL;
        const int r = i - k * NREL;
        Wt[r][k] = W2[i];
    }
    __syncthreads();

    const int warp = tid >> 5;
    const int lane = tid & 31;
    const int c = blockIdx.x * 8 + warp;

    const float* hrow = g_h + (size_t)c * HID;
    float acc[NREL];
    #pragma unroll
    for (int r = 0; r < NREL; ++r) acc[r] = 0.0f;

    #pragma unroll 4
    for (int i = 0; i < 32; ++i) {
        const int k = i * 32 + lane;
        const float hv = hrow[k];
        #pragma unroll
        for (int r = 0; r < NREL; ++r) acc[r] += hv * Wt[r][k];
    }

    #pragma unroll
    for (int r = 0; r < NREL; ++r) {
        #pragma unroll
        for (int off = 16; off > 0; off >>= 1)
            acc[r] += __shfl_down_sync(0xffffffffu, acc[r], off);
    }

    if (lane == 0) {
        float lg[NREL];
        float mx = -1e30f;
        #pragma unroll
        for (int r = 0; r < NREL; ++r) {
            lg[r] = acc[r] + b2[r];
            mx = fmaxf(mx, lg[r]);
        }
        float s = 0.0f;
        #pragma unroll
        for (int r = 0; r < NREL; ++r) s += expf(lg[r] - mx);
        const float lse = logf(s) + mx;

        const int lbl = labels[c];
        g_loss[c] = lse - lg[lbl];

        float* dst = logits_out + (size_t)c * NREL;
        #pragma unroll
        for (int r = 0; r < NREL; ++r) dst[r] = lg[r];
    }
}

// ============================================================================
// Kernel 4: loss = mean(g_loss)  -- single block, fixed-order tree
// ============================================================================
__global__ void reduce_loss_kernel(float* __restrict__ loss_out) {
    __shared__ float sm[1024];
    const int tid = threadIdx.x;
    float s = 0.0f;
    #pragma unroll
    for (int i = 0; i < 32; ++i) s += g_loss[tid + (i << 10)];
    sm[tid] = s;
    __syncthreads();
    for (int off = 512; off > 0; off >>= 1) {
        if (tid < off) sm[tid] += sm[tid + off];
        __syncthreads();
    }
    if (tid == 0) loss_out[0] = sm[0] * (1.0f / (float)C_CAND);
}

// ============================================================================
// launch
// ============================================================================
extern "C" void kernel_launch(void* const* d_in, const int* in_sizes, int n_in,
                              void* d_out, int out_size) {
    const float* emb    = (const float*)d_in[0];   // [100000, 1024]
    const int*   src    = (const int*)d_in[1];     // [32768]
    const int*   dst    = (const int*)d_in[2];     // [32768]
    const int*   labels = (const int*)d_in[3];     // [32768]
    const float* W1     = (const float*)d_in[4];   // [4096, 1024]
    const float* b1     = (const float*)d_in[5];   // [1024]
    const float* W2     = (const float*)d_in[6];   // [1024, 10]
    const float* b2     = (const float*)d_in[7];   // [10]

    float* out = (float*)d_out;
    float* logits_dst;
    float* loss_dst = nullptr;

    if (out_size >= C_CAND * NREL + 1) {
        loss_dst   = out;
        logits_dst = out + 1;
    } else if (out_size == C_CAND * NREL) {
        logits_dst = out;
    } else {
        void* p = nullptr;
        cudaGetSymbolAddress(&p, g_logits_sink);
        logits_dst = (float*)p;
        loss_dst   = out;
    }

    cudaFuncSetAttribute(gemm1_mma_kernel,
                         cudaFuncAttributeMaxDynamicSharedMemorySize, GEMM_SMEM);

    dim3 gw(K4 / 32, HID / 32);
    wsplit_kernel<<<gw, dim3(32, 8)>>>(W1);

    build_feats_kernel<<<C_CAND, 256>>>(emb, src, dst);

    dim3 gg(HID / 128, C_CAND / 128);   // (8, 256), x = N tile
    gemm1_mma_kernel<<<gg, 256, GEMM_SMEM>>>(b1);

    head_kernel<<<C_CAND / 8, 256>>>(W2, b2, labels, logits_dst);

    if (loss_dst) reduce_loss_kernel<<<1, 1024>>>(loss_dst);
}

// round 9
// speedup vs baseline: 2.2696x; 1.0209x over previous
#include <cuda_runtime.h>
#include <cuda_bf16.h>
#include <cstdint>
#include <math.h>

typedef unsigned long long ull;

#define C_CAND 32768
#define HID    1024
#define K4     4096
#define NREL   10

// ---- scratch (static device globals; no allocations anywhere) ----
__device__ __align__(16) __nv_bfloat16 g_fHi[(size_t)C_CAND * K4];   // 256 MB feats hi
__device__ __align__(16) __nv_bfloat16 g_fLo[(size_t)C_CAND * K4];   // 256 MB feats lo
__device__ __align__(16) __nv_bfloat16 g_wHi[(size_t)HID * K4];      // 8 MB  W1^T hi [n][k]
__device__ __align__(16) __nv_bfloat16 g_wLo[(size_t)HID * K4];      // 8 MB  W1^T lo
__device__ __align__(16) float g_h[(size_t)C_CAND * HID];            // 128 MB
__device__ float g_loss[C_CAND];
__device__ float g_logits_sink[(size_t)C_CAND * NREL];

__device__ __forceinline__ float gelu_exact(float x) {
    return 0.5f * x * (1.0f + erff(x * 0.70710678118654752440f));
}

// ============================ PTX helpers (sm_80+ base-target only) =========
__device__ __forceinline__ uint32_t smem_u32(const void* p) {
    uint32_t a;
    asm("{ .reg .u64 t; cvta.to.shared.u64 t, %1; cvt.u32.u64 %0, t; }" : "=r"(a) : "l"(p));
    return a;
}
__device__ __forceinline__ void cpasync16(uint32_t dst, const void* src) {
    asm volatile("cp.async.cg.shared.global [%0], [%1], 16;" :: "r"(dst), "l"(src));
}
__device__ __forceinline__ void ldsm4(uint32_t& r0, uint32_t& r1, uint32_t& r2,
                                      uint32_t& r3, uint32_t addr) {
    asm volatile("ldmatrix.sync.aligned.m8n8.x4.shared.b16 {%0,%1,%2,%3}, [%4];"
                 : "=r"(r0), "=r"(r1), "=r"(r2), "=r"(r3) : "r"(addr));
}
__device__ __forceinline__ void mma16816(float* c, const uint32_t* a, const uint32_t* b) {
    asm volatile(
        "mma.sync.aligned.m16n8k16.row.col.f32.bf16.bf16.f32 "
        "{%0,%1,%2,%3}, {%4,%5,%6,%7}, {%8,%9}, {%0,%1,%2,%3};"
        : "+f"(c[0]), "+f"(c[1]), "+f"(c[2]), "+f"(c[3])
        : "r"(a[0]), "r"(a[1]), "r"(a[2]), "r"(a[3]), "r"(b[0]), "r"(b[1]));
}

// ============================================================================
// Kernel 0: transpose + bf16-split W1 -> g_wHi/g_wLo as [N=1024][K=4096]
// ============================================================================
__global__ void wsplit_kernel(const float* __restrict__ W1) {
    __shared__ float sm[32][33];
    const int k0 = blockIdx.x * 32;
    const int n0 = blockIdx.y * 32;
    const int tx = threadIdx.x, ty = threadIdx.y;   // 32 x 8
    #pragma unroll
    for (int i = 0; i < 4; ++i)
        sm[ty + i * 8][tx] = W1[(size_t)(k0 + ty + i * 8) * HID + n0 + tx];
    __syncthreads();
    #pragma unroll
    for (int i = 0; i < 4; ++i) {
        const int n = ty + i * 8;
        const float v = sm[tx][n];                  // = W1[k0+tx][n0+n]
        const __nv_bfloat16 hb = __float2bfloat16_rn(v);
        const float lo = v - __bfloat162float(hb);
        const size_t o = (size_t)(n0 + n) * K4 + k0 + tx;
        g_wHi[o] = hb;
        g_wLo[o] = __float2bfloat16_rn(lo);
    }
}

// ============================================================================
// Kernel 1: gather + build feats, split to bf16 hi/lo   [C, 4H]
// ============================================================================
__device__ __forceinline__ void split_store4(float4 v, size_t elem_off) {
    unsigned short h0 = __bfloat16_as_ushort(__float2bfloat16_rn(v.x));
    unsigned short h1 = __bfloat16_as_ushort(__float2bfloat16_rn(v.y));
    unsigned short h2 = __bfloat16_as_ushort(__float2bfloat16_rn(v.z));
    unsigned short h3 = __bfloat16_as_ushort(__float2bfloat16_rn(v.w));
    float r0 = v.x - __bfloat162float(__ushort_as_bfloat16(h0));
    float r1 = v.y - __bfloat162float(__ushort_as_bfloat16(h1));
    float r2 = v.z - __bfloat162float(__ushort_as_bfloat16(h2));
    float r3 = v.w - __bfloat162float(__ushort_as_bfloat16(h3));
    unsigned short l0 = __bfloat16_as_ushort(__float2bfloat16_rn(r0));
    unsigned short l1 = __bfloat16_as_ushort(__float2bfloat16_rn(r1));
    unsigned short l2 = __bfloat16_as_ushort(__float2bfloat16_rn(r2));
    unsigned short l3 = __bfloat16_as_ushort(__float2bfloat16_rn(r3));
    uint2 hi, lo;
    hi.x = (uint32_t)h0 | ((uint32_t)h1 << 16);
    hi.y = (uint32_t)h2 | ((uint32_t)h3 << 16);
    lo.x = (uint32_t)l0 | ((uint32_t)l1 << 16);
    lo.y = (uint32_t)l2 | ((uint32_t)l3 << 16);
    *(uint2*)(g_fHi + elem_off) = hi;
    *(uint2*)(g_fLo + elem_off) = lo;
}

__global__ void build_feats_kernel(const float* __restrict__ emb,
                                   const int* __restrict__ src_idx,
                                   const int* __restrict__ dst_idx) {
    const int c = blockIdx.x;
    const int h = threadIdx.x << 2;                 // 0..1020
    const int si = src_idx[c];
    const int di = dst_idx[c];

    const float4 s = *(const float4*)(emb + (size_t)si * HID + h);
    const float4 d = *(const float4*)(emb + (size_t)di * HID + h);

    float4 ad, pd;
    ad.x = fabsf(s.x - d.x); ad.y = fabsf(s.y - d.y);
    ad.z = fabsf(s.z - d.z); ad.w = fabsf(s.w - d.w);
    pd.x = s.x * d.x; pd.y = s.y * d.y; pd.z = s.z * d.z; pd.w = s.w * d.w;

    const size_t base = (size_t)c * K4;
    split_store4(s,  base + h);
    split_store4(d,  base + HID + h);
    split_store4(ad, base + 2 * HID + h);
    split_store4(pd, base + 3 * HID + h);
}

// ============================================================================
// Kernel 2: h = gelu(feats @ W1 + b1) via mma.sync bf16 3-product emulation
// CTA tile 256x128, Kc=64, 2-stage cp.async pipeline (96KB/stage, 192KB smem).
// 8 warps as 4(M)x2(N); warp tile 64x64. Per k16 per warp: 16 LDSM.x4, 96 HMMA
//   -> 83 B smem traffic per MMA (was 128).
// ============================================================================
#define BM          256
#define BN          128
#define BK          64
#define STG_BYTES   98304    // Ahi 32K | Alo 32K | Bhi 16K | Blo 16K
#define OFF_AHI     0
#define OFF_ALO     32768
#define OFF_BHI     65536
#define OFF_BLO     81920
#define GEMM_SMEM   (2 * STG_BYTES)

__device__ __forceinline__ void load_stage(int t, int slot, int tid, int m0, int n0,
                                           uint32_t sb) {
    const int k0 = t * BK;
    const uint32_t st = sb + slot * STG_BYTES;
    // A: 256 rows x 128B (hi/lo)
    #pragma unroll
    for (int i = 0; i < 8; ++i) {
        const int idx = i * 256 + tid;         // 0..2047
        const int r = idx >> 3;                // row 0..255
        const int c = idx & 7;                 // 16B chunk
        const uint32_t d = st + r * 128 + ((c ^ (r & 7)) << 4);
        const size_t go = (size_t)(m0 + r) * K4 + k0 + c * 8;
        cpasync16(d + OFF_AHI, g_fHi + go);
        cpasync16(d + OFF_ALO, g_fLo + go);
    }
    // B: 128 rows x 128B (hi/lo)
    #pragma unroll
    for (int i = 0; i < 4; ++i) {
        const int idx = i * 256 + tid;         // 0..1023
        const int r = idx >> 3;                // row 0..127
        const int c = idx & 7;
        const uint32_t d = st + r * 128 + ((c ^ (r & 7)) << 4);
        const size_t go = (size_t)(n0 + r) * K4 + k0 + c * 8;
        cpasync16(d + OFF_BHI, g_wHi + go);
        cpasync16(d + OFF_BLO, g_wLo + go);
    }
}

__global__ void __launch_bounds__(256, 1)
gemm1_mma_kernel(const float* __restrict__ b1) {
    extern __shared__ __align__(128) char smem[];
    const uint32_t sb = smem_u32(smem);
    const int tid  = threadIdx.x;
    const int lane = tid & 31;
    const int wrp  = tid >> 5;
    const int n0 = blockIdx.x * BN;      // x fastest: N tiles of one M block co-run
    const int m0 = blockIdx.y * BM;

    const int m_off = (wrp & 3) * 64;    // warp M origin
    const int n_off = (wrp >> 2) * 64;   // warp N origin

    const int l15 = lane & 15;
    const int lhf = lane >> 4;
    const int l7  = lane & 7;
    uint32_t rowA[4], rowB[4], swk[4];
    #pragma unroll
    for (int mt = 0; mt < 4; ++mt) rowA[mt] = (uint32_t)(m_off + mt * 16 + l15) * 128;
    #pragma unroll
    for (int nt = 0; nt < 4; ++nt) rowB[nt] = (uint32_t)(n_off + nt * 16 + l15) * 128;
    #pragma unroll
    for (int kk = 0; kk < 4; ++kk) swk[kk] = (uint32_t)(((2 * kk + lhf) ^ l7) << 4);

    float acc[4][8][4];
    #pragma unroll
    for (int mt = 0; mt < 4; ++mt)
        #pragma unroll
        for (int j = 0; j < 8; ++j)
            #pragma unroll
            for (int q = 0; q < 4; ++q) acc[mt][j][q] = 0.0f;

    load_stage(0, 0, tid, m0, n0, sb);
    asm volatile("cp.async.commit_group;" ::: "memory");
    load_stage(1, 1, tid, m0, n0, sb);
    asm volatile("cp.async.commit_group;" ::: "memory");

    const int NT = K4 / BK;   // 64
    for (int t = 0; t < NT; ++t) {
        const int slot = t & 1;
        asm volatile("cp.async.wait_group 1;" ::: "memory");
        __syncthreads();

        const uint32_t st = sb + slot * STG_BYTES;
        #pragma unroll
        for (int kk = 0; kk < 4; ++kk) {
            uint32_t aH[4][4], aL[4][4];
            #pragma unroll
            for (int mt = 0; mt < 4; ++mt) {
                ldsm4(aH[mt][0], aH[mt][1], aH[mt][2], aH[mt][3],
                      st + OFF_AHI + rowA[mt] + swk[kk]);
                ldsm4(aL[mt][0], aL[mt][1], aL[mt][2], aL[mt][3],
                      st + OFF_ALO + rowA[mt] + swk[kk]);
            }
            #pragma unroll
            for (int nt = 0; nt < 4; ++nt) {
                uint32_t bH[2][2], bL[2][2];
                uint32_t r0, r1, r2, r3;
                ldsm4(r0, r1, r2, r3, st + OFF_BHI + rowB[nt] + swk[kk]);
                bH[0][0] = r0; bH[0][1] = r2; bH[1][0] = r1; bH[1][1] = r3;
                ldsm4(r0, r1, r2, r3, st + OFF_BLO + rowB[nt] + swk[kk]);
                bL[0][0] = r0; bL[0][1] = r2; bL[1][0] = r1; bL[1][1] = r3;
                #pragma unroll
                for (int mt = 0; mt < 4; ++mt) {
                    #pragma unroll
                    for (int u = 0; u < 2; ++u) {
                        float* cc = acc[mt][2 * nt + u];
                        mma16816(cc, aH[mt], bH[u]);
                        mma16816(cc, aH[mt], bL[u]);
                        mma16816(cc, aL[mt], bH[u]);
                    }
                }
            }
        }
        __syncthreads();

        if (t + 2 < NT) load_stage(t + 2, slot, tid, m0, n0, sb);
        asm volatile("cp.async.commit_group;" ::: "memory");
    }

    // epilogue: + bias, exact GELU, direct global stores (float2)
    const int mrow = m0 + m_off + (lane >> 2);
    const int col0 = n0 + n_off + 2 * (lane & 3);
    float bb0[8], bb1[8];
    #pragma unroll
    for (int j = 0; j < 8; ++j) {
        bb0[j] = __ldg(b1 + col0 + j * 8);
        bb1[j] = __ldg(b1 + col0 + j * 8 + 1);
    }
    #pragma unroll
    for (int mt = 0; mt < 4; ++mt) {
        const int r = mrow + mt * 16;
        #pragma unroll
        for (int j = 0; j < 8; ++j) {
            const int c = col0 + j * 8;
            float2 v0, v1;
            v0.x = gelu_exact(acc[mt][j][0] + bb0[j]);
            v0.y = gelu_exact(acc[mt][j][1] + bb1[j]);
            v1.x = gelu_exact(acc[mt][j][2] + bb0[j]);
            v1.y = gelu_exact(acc[mt][j][3] + bb1[j]);
            *(float2*)(g_h + (size_t)r * HID + c)       = v0;
            *(float2*)(g_h + (size_t)(r + 8) * HID + c) = v1;
        }
    }
}

// ============================================================================
// Kernel 3: logits = h @ W2 + b2 ; log-softmax ; NLL
// 32 candidates/block (4 per warp); vectorized LDS.128/LDG.128 inner loop.
// ============================================================================
__global__ __launch_bounds__(256)
void head_kernel(const float* __restrict__ W2, const float* __restrict__ b2,
                 const int* __restrict__ labels, float* __restrict__ logits_out) {
    __shared__ float Wt[NREL][HID];   // 40 KB

    const int tid = threadIdx.x;
    for (int i = tid; i < NREL * HID; i += 256) {
        const int k = i / NREL;
        const int r = i - k * NREL;
        Wt[r][k] = W2[i];
    }
    __syncthreads();

    const int warp = tid >> 5;
    const int lane = tid & 31;
    const int cbase = blockIdx.x * 32 + warp * 4;

    #pragma unroll 1
    for (int cc = 0; cc < 4; ++cc) {
        const int c = cbase + cc;
        const float* hrow = g_h + (size_t)c * HID;

        float acc[NREL];
        #pragma unroll
        for (int r = 0; r < NREL; ++r) acc[r] = 0.0f;

        #pragma unroll
        for (int i = 0; i < 8; ++i) {
            const int k = (i * 32 + lane) * 4;      // float4 index
            const float4 hv = *(const float4*)(hrow + k);
            #pragma unroll
            for (int r = 0; r < NREL; ++r) {
                const float4 w = *(const float4*)&Wt[r][k];
                acc[r] += hv.x * w.x + hv.y * w.y + hv.z * w.z + hv.w * w.w;
            }
        }

        #pragma unroll
        for (int r = 0; r < NREL; ++r) {
            #pragma unroll
            for (int off = 16; off > 0; off >>= 1)
                acc[r] += __shfl_down_sync(0xffffffffu, acc[r], off);
        }

        if (lane == 0) {
            float lg[NREL];
            float mx = -1e30f;
            #pragma unroll
            for (int r = 0; r < NREL; ++r) {
                lg[r] = acc[r] + b2[r];
                mx = fmaxf(mx, lg[r]);
            }
            float s = 0.0f;
            #pragma unroll
            for (int r = 0; r < NREL; ++r) s += expf(lg[r] - mx);
            const float lse = logf(s) + mx;

            const int lbl = labels[c];
            g_loss[c] = lse - lg[lbl];

            float* dst = logits_out + (size_t)c * NREL;
            #pragma unroll
            for (int r = 0; r < NREL; ++r) dst[r] = lg[r];
        }
    }
}

// ============================================================================
// Kernel 4: loss = mean(g_loss)  -- single block, fixed-order tree
// ============================================================================
__global__ void reduce_loss_kernel(float* __restrict__ loss_out) {
    __shared__ float sm[1024];
    const int tid = threadIdx.x;
    float s = 0.0f;
    #pragma unroll
    for (int i = 0; i < 32; ++i) s += g_loss[tid + (i << 10)];
    sm[tid] = s;
    __syncthreads();
    for (int off = 512; off > 0; off >>= 1) {
        if (tid < off) sm[tid] += sm[tid + off];
        __syncthreads();
    }
    if (tid == 0) loss_out[0] = sm[0] * (1.0f / (float)C_CAND);
}

// ============================================================================
// launch
// ============================================================================
extern "C" void kernel_launch(void* const* d_in, const int* in_sizes, int n_in,
                              void* d_out, int out_size) {
    const float* emb    = (const float*)d_in[0];   // [100000, 1024]
    const int*   src    = (const int*)d_in[1];     // [32768]
    const int*   dst    = (const int*)d_in[2];     // [32768]
    const int*   labels = (const int*)d_in[3];     // [32768]
    const float* W1     = (const float*)d_in[4];   // [4096, 1024]
    const float* b1     = (const float*)d_in[5];   // [1024]
    const float* W2     = (const float*)d_in[6];   // [1024, 10]
    const float* b2     = (const float*)d_in[7];   // [10]

    float* out = (float*)d_out;
    float* logits_dst;
    float* loss_dst = nullptr;

    if (out_size >= C_CAND * NREL + 1) {
        loss_dst   = out;
        logits_dst = out + 1;
    } else if (out_size == C_CAND * NREL) {
        logits_dst = out;
    } else {
        void* p = nullptr;
        cudaGetSymbolAddress(&p, g_logits_sink);
        logits_dst = (float*)p;
        loss_dst   = out;
    }

    cudaFuncSetAttribute(gemm1_mma_kernel,
                         cudaFuncAttributeMaxDynamicSharedMemorySize, GEMM_SMEM);

    dim3 gw(K4 / 32, HID / 32);
    wsplit_kernel<<<gw, dim3(32, 8)>>>(W1);

    build_feats_kernel<<<C_CAND, 256>>>(emb, src, dst);

    dim3 gg(HID / BN, C_CAND / BM);    // (8, 128), x = N tile
    gemm1_mma_kernel<<<gg, 256, GEMM_SMEM>>>(b1);

    head_kernel<<<C_CAND / 32, 256>>>(W2, b2, labels, logits_dst);

    if (loss_dst) reduce_loss_kernel<<<1, 1024>>>(loss_dst);
}

// round 10
// speedup vs baseline: 2.3636x; 1.0414x over previous
#include <cuda_runtime.h>
#include <cuda_bf16.h>
#include <cstdint>
#include <math.h>

typedef unsigned long long ull;

#define C_CAND 32768
#define HID    1024
#define K4     4096
#define NREL   10

// ---- scratch (static device globals; no allocations anywhere) ----
__device__ __align__(16) __nv_bfloat16 g_fHi[(size_t)C_CAND * K4];   // 256 MB feats hi
__device__ __align__(16) __nv_bfloat16 g_fLo[(size_t)C_CAND * K4];   // 256 MB feats lo
__device__ __align__(16) __nv_bfloat16 g_wHi[(size_t)HID * K4];      // 8 MB  W1^T hi [n][k]
__device__ __align__(16) __nv_bfloat16 g_wLo[(size_t)HID * K4];      // 8 MB  W1^T lo
__device__ __align__(16) float g_h[(size_t)C_CAND * HID];            // 128 MB
__device__ float g_loss[C_CAND];
__device__ float g_logits_sink[(size_t)C_CAND * NREL];

__device__ __forceinline__ float gelu_exact(float x) {
    return 0.5f * x * (1.0f + erff(x * 0.70710678118654752440f));
}

// ============================ PTX helpers (sm_80+ base-target only) =========
__device__ __forceinline__ uint32_t smem_u32(const void* p) {
    uint32_t a;
    asm("{ .reg .u64 t; cvta.to.shared.u64 t, %1; cvt.u32.u64 %0, t; }" : "=r"(a) : "l"(p));
    return a;
}
__device__ __forceinline__ void cpasync16(uint32_t dst, const void* src) {
    asm volatile("cp.async.cg.shared.global [%0], [%1], 16;" :: "r"(dst), "l"(src));
}
__device__ __forceinline__ void ldsm4(uint32_t& r0, uint32_t& r1, uint32_t& r2,
                                      uint32_t& r3, uint32_t addr) {
    asm volatile("ldmatrix.sync.aligned.m8n8.x4.shared.b16 {%0,%1,%2,%3}, [%4];"
                 : "=r"(r0), "=r"(r1), "=r"(r2), "=r"(r3) : "r"(addr));
}
__device__ __forceinline__ void mma16816(float* c, const uint32_t* a, const uint32_t* b) {
    asm volatile(
        "mma.sync.aligned.m16n8k16.row.col.f32.bf16.bf16.f32 "
        "{%0,%1,%2,%3}, {%4,%5,%6,%7}, {%8,%9}, {%0,%1,%2,%3};"
        : "+f"(c[0]), "+f"(c[1]), "+f"(c[2]), "+f"(c[3])
        : "r"(a[0]), "r"(a[1]), "r"(a[2]), "r"(a[3]), "r"(b[0]), "r"(b[1]));
}

// ============================================================================
// Kernel 0: transpose + bf16-split W1 -> g_wHi/g_wLo as [N=1024][K=4096]
// ============================================================================
__global__ void wsplit_kernel(const float* __restrict__ W1) {
    __shared__ float sm[32][33];
    const int k0 = blockIdx.x * 32;
    const int n0 = blockIdx.y * 32;
    const int tx = threadIdx.x, ty = threadIdx.y;   // 32 x 8
    #pragma unroll
    for (int i = 0; i < 4; ++i)
        sm[ty + i * 8][tx] = W1[(size_t)(k0 + ty + i * 8) * HID + n0 + tx];
    __syncthreads();
    #pragma unroll
    for (int i = 0; i < 4; ++i) {
        const int n = ty + i * 8;
        const float v = sm[tx][n];                  // = W1[k0+tx][n0+n]
        const __nv_bfloat16 hb = __float2bfloat16_rn(v);
        const float lo = v - __bfloat162float(hb);
        const size_t o = (size_t)(n0 + n) * K4 + k0 + tx;
        g_wHi[o] = hb;
        g_wLo[o] = __float2bfloat16_rn(lo);
    }
}

// ============================================================================
// Kernel 1: gather + build feats, split to bf16 hi/lo   [C, 4H]
// ============================================================================
__device__ __forceinline__ void split_store4(float4 v, size_t elem_off) {
    unsigned short h0 = __bfloat16_as_ushort(__float2bfloat16_rn(v.x));
    unsigned short h1 = __bfloat16_as_ushort(__float2bfloat16_rn(v.y));
    unsigned short h2 = __bfloat16_as_ushort(__float2bfloat16_rn(v.z));
    unsigned short h3 = __bfloat16_as_ushort(__float2bfloat16_rn(v.w));
    float r0 = v.x - __bfloat162float(__ushort_as_bfloat16(h0));
    float r1 = v.y - __bfloat162float(__ushort_as_bfloat16(h1));
    float r2 = v.z - __bfloat162float(__ushort_as_bfloat16(h2));
    float r3 = v.w - __bfloat162float(__ushort_as_bfloat16(h3));
    unsigned short l0 = __bfloat16_as_ushort(__float2bfloat16_rn(r0));
    unsigned short l1 = __bfloat16_as_ushort(__float2bfloat16_rn(r1));
    unsigned short l2 = __bfloat16_as_ushort(__float2bfloat16_rn(r2));
    unsigned short l3 = __bfloat16_as_ushort(__float2bfloat16_rn(r3));
    uint2 hi, lo;
    hi.x = (uint32_t)h0 | ((uint32_t)h1 << 16);
    hi.y = (uint32_t)h2 | ((uint32_t)h3 << 16);
    lo.x = (uint32_t)l0 | ((uint32_t)l1 << 16);
    lo.y = (uint32_t)l2 | ((uint32_t)l3 << 16);
    *(uint2*)(g_fHi + elem_off) = hi;
    *(uint2*)(g_fLo + elem_off) = lo;
}

__global__ void build_feats_kernel(const float* __restrict__ emb,
                                   const int* __restrict__ src_idx,
                                   const int* __restrict__ dst_idx) {
    const int c = blockIdx.x;
    const int h = threadIdx.x << 2;                 // 0..1020
    const int si = src_idx[c];
    const int di = dst_idx[c];

    const float4 s = *(const float4*)(emb + (size_t)si * HID + h);
    const float4 d = *(const float4*)(emb + (size_t)di * HID + h);

    float4 ad, pd;
    ad.x = fabsf(s.x - d.x); ad.y = fabsf(s.y - d.y);
    ad.z = fabsf(s.z - d.z); ad.w = fabsf(s.w - d.w);
    pd.x = s.x * d.x; pd.y = s.y * d.y; pd.z = s.z * d.z; pd.w = s.w * d.w;

    const size_t base = (size_t)c * K4;
    split_store4(s,  base + h);
    split_store4(d,  base + HID + h);
    split_store4(ad, base + 2 * HID + h);
    split_store4(pd, base + 3 * HID + h);
}

// ============================================================================
// Kernel 2: h = gelu(feats @ W1 + b1) via mma.sync bf16 3-product emulation
// CTA tile 128x128, Kc=32, 3-stage cp.async pipe (32KB/stage, 96KB/CTA)
//   -> 2 CTAs/SM (4 warps/SMSP) for latency hiding on the HMMA path.
// 8 warps as 4(M)x2(N); warp tile 32x64. 64B smem rows, xor swizzle
//   chunk ^= (row>>1)&3  (conflict-free for ldsm 8-row phases and cp.async).
// One __syncthreads per k-iter (3-stage reuse distance makes it safe).
// ============================================================================
#define BM          128
#define BN          128
#define BK          32
#define NSTAGE      3
#define STG_BYTES   32768    // Ahi 8K | Alo 8K | Bhi 8K | Blo 8K
#define OFF_AHI     0
#define OFF_ALO     8192
#define OFF_BHI     16384
#define OFF_BLO     24576
#define GEMM_SMEM   (NSTAGE * STG_BYTES)

__device__ __forceinline__ void load_stage(int t, int slot, int tid, int m0, int n0,
                                           uint32_t sb) {
    const int k0 = t * BK;
    const uint32_t st = sb + slot * STG_BYTES;
    #pragma unroll
    for (int i = 0; i < 2; ++i) {
        const int idx = i * 256 + tid;         // 0..511
        const int r = idx >> 2;                // row 0..127
        const int c = idx & 3;                 // 16B chunk 0..3
        const uint32_t d = st + r * 64 + ((c ^ ((r >> 1) & 3)) << 4);
        const size_t goA = (size_t)(m0 + r) * K4 + k0 + c * 8;
        const size_t goB = (size_t)(n0 + r) * K4 + k0 + c * 8;
        cpasync16(d + OFF_AHI, g_fHi + goA);
        cpasync16(d + OFF_ALO, g_fLo + goA);
        cpasync16(d + OFF_BHI, g_wHi + goB);
        cpasync16(d + OFF_BLO, g_wLo + goB);
    }
}

__global__ void __launch_bounds__(256, 2)
gemm1_mma_kernel(const float* __restrict__ b1) {
    extern __shared__ __align__(128) char smem[];
    const uint32_t sb = smem_u32(smem);
    const int tid  = threadIdx.x;
    const int lane = tid & 31;
    const int wrp  = tid >> 5;
    const int n0 = blockIdx.x * BN;      // x fastest: N tiles of one M block co-run
    const int m0 = blockIdx.y * BM;

    const int m_off = (wrp & 3) * 32;    // warp M origin
    const int n_off = (wrp >> 2) * 64;   // warp N origin

    const int l15 = lane & 15;
    const int lhf = lane >> 4;           // 0/1: selects 16B chunk within 16-col block

    // per-fragment-row base byte offsets + row-dependent swizzle field
    uint32_t rAb[2], rBb[4];
    uint32_t rAs[2], rBs[4];
    #pragma unroll
    for (int mt = 0; mt < 2; ++mt) {
        const int r = m_off + mt * 16 + l15;
        rAb[mt] = (uint32_t)r * 64;
        rAs[mt] = (uint32_t)((r >> 1) & 3);
    }
    #pragma unroll
    for (int nt = 0; nt < 4; ++nt) {
        const int r = n_off + nt * 16 + l15;
        rBb[nt] = (uint32_t)r * 64;
        rBs[nt] = (uint32_t)((r >> 1) & 3);
    }

    float acc[2][8][4];
    #pragma unroll
    for (int mt = 0; mt < 2; ++mt)
        #pragma unroll
        for (int j = 0; j < 8; ++j)
            #pragma unroll
            for (int q = 0; q < 4; ++q) acc[mt][j][q] = 0.0f;

    load_stage(0, 0, tid, m0, n0, sb);
    asm volatile("cp.async.commit_group;" ::: "memory");
    load_stage(1, 1, tid, m0, n0, sb);
    asm volatile("cp.async.commit_group;" ::: "memory");

    const int NT = K4 / BK;   // 128
    int slot = 0, nslot = 2;
    for (int t = 0; t < NT; ++t) {
        asm volatile("cp.async.wait_group 1;" ::: "memory");
        __syncthreads();

        if (t + 2 < NT) load_stage(t + 2, nslot, tid, m0, n0, sb);
        asm volatile("cp.async.commit_group;" ::: "memory");

        const uint32_t st = sb + slot * STG_BYTES;
        #pragma unroll
        for (int kk = 0; kk < 2; ++kk) {
            const uint32_t ck = (uint32_t)(kk * 2 + lhf);
            uint32_t aH[2][4], aL[2][4];
            #pragma unroll
            for (int mt = 0; mt < 2; ++mt) {
                const uint32_t ao = rAb[mt] + ((ck ^ rAs[mt]) << 4);
                ldsm4(aH[mt][0], aH[mt][1], aH[mt][2], aH[mt][3], st + OFF_AHI + ao);
                ldsm4(aL[mt][0], aL[mt][1], aL[mt][2], aL[mt][3], st + OFF_ALO + ao);
            }
            #pragma unroll
            for (int nt = 0; nt < 4; ++nt) {
                const uint32_t bo = rBb[nt] + ((ck ^ rBs[nt]) << 4);
                uint32_t bH[2][2], bL[2][2];
                uint32_t r0, r1, r2, r3;
                ldsm4(r0, r1, r2, r3, st + OFF_BHI + bo);
                bH[0][0] = r0; bH[0][1] = r2; bH[1][0] = r1; bH[1][1] = r3;
                ldsm4(r0, r1, r2, r3, st + OFF_BLO + bo);
                bL[0][0] = r0; bL[0][1] = r2; bL[1][0] = r1; bL[1][1] = r3;
                #pragma unroll
                for (int mt = 0; mt < 2; ++mt) {
                    #pragma unroll
                    for (int u = 0; u < 2; ++u) {
                        float* cc = acc[mt][2 * nt + u];
                        mma16816(cc, aH[mt], bH[u]);
                        mma16816(cc, aH[mt], bL[u]);
                        mma16816(cc, aL[mt], bH[u]);
                    }
                }
            }
        }

        slot = slot + 1 == NSTAGE ? 0 : slot + 1;
        nslot = nslot + 1 == NSTAGE ? 0 : nslot + 1;
    }

    // epilogue: + bias, exact GELU, direct global stores (float2)
    const int mrow = m0 + m_off + (lane >> 2);
    const int col0 = n0 + n_off + 2 * (lane & 3);
    #pragma unroll
    for (int mt = 0; mt < 2; ++mt) {
        const int r = mrow + mt * 16;
        #pragma unroll
        for (int j = 0; j < 8; ++j) {
            const int c = col0 + j * 8;
            const float bb0 = __ldg(b1 + c);
            const float bb1 = __ldg(b1 + c + 1);
            float2 v0, v1;
            v0.x = gelu_exact(acc[mt][j][0] + bb0);
            v0.y = gelu_exact(acc[mt][j][1] + bb1);
            v1.x = gelu_exact(acc[mt][j][2] + bb0);
            v1.y = gelu_exact(acc[mt][j][3] + bb1);
            *(float2*)(g_h + (size_t)r * HID + c)       = v0;
            *(float2*)(g_h + (size_t)(r + 8) * HID + c) = v1;
        }
    }
}

// ============================================================================
// Kernel 3: logits = h @ W2 + b2 ; log-softmax ; NLL
// 1 candidate per warp, float4 LDS/LDG (low register pressure).
// ============================================================================
__global__ __launch_bounds__(256)
void head_kernel(const float* __restrict__ W2, const float* __restrict__ b2,
                 const int* __restrict__ labels, float* __restrict__ logits_out) {
    __shared__ float Wt[NREL][HID];   // 40 KB

    const int tid = threadIdx.x;
    for (int i = tid; i < NREL * HID; i += 256) {
        const int k = i / NREL;
        const int r = i - k * NREL;
        Wt[r][k] = W2[i];
    }
    __syncthreads();

    const int warp = tid >> 5;
    const int lane = tid & 31;
    const int c = blockIdx.x * 8 + warp;
    const float* hrow = g_h + (size_t)c * HID;

    float acc[NREL];
    #pragma unroll
    for (int r = 0; r < NREL; ++r) acc[r] = 0.0f;

    #pragma unroll
    for (int i = 0; i < 8; ++i) {
        const int k = (i * 32 + lane) * 4;      // float4 index, coalesced
        const float4 hv = *(const float4*)(hrow + k);
        #pragma unroll
        for (int r = 0; r < NREL; ++r) {
            const float4 w = *(const float4*)&Wt[r][k];
            acc[r] += hv.x * w.x + hv.y * w.y + hv.z * w.z + hv.w * w.w;
        }
    }

    #pragma unroll
    for (int r = 0; r < NREL; ++r) {
        #pragma unroll
        for (int off = 16; off > 0; off >>= 1)
            acc[r] += __shfl_down_sync(0xffffffffu, acc[r], off);
    }

    if (lane == 0) {
        float lg[NREL];
        float mx = -1e30f;
        #pragma unroll
        for (int r = 0; r < NREL; ++r) {
            lg[r] = acc[r] + b2[r];
            mx = fmaxf(mx, lg[r]);
        }
        float s = 0.0f;
        #pragma unroll
        for (int r = 0; r < NREL; ++r) s += expf(lg[r] - mx);
        const float lse = logf(s) + mx;

        const int lbl = labels[c];
        g_loss[c] = lse - lg[lbl];

        float* dst = logits_out + (size_t)c * NREL;
        #pragma unroll
        for (int r = 0; r < NREL; ++r) dst[r] = lg[r];
    }
}

// ============================================================================
// Kernel 4: loss = mean(g_loss)  -- single block, fixed-order tree
// ============================================================================
__global__ void reduce_loss_kernel(float* __restrict__ loss_out) {
    __shared__ float sm[1024];
    const int tid = threadIdx.x;
    float s = 0.0f;
    #pragma unroll
    for (int i = 0; i < 32; ++i) s += g_loss[tid + (i << 10)];
    sm[tid] = s;
    __syncthreads();
    for (int off = 512; off > 0; off >>= 1) {
        if (tid < off) sm[tid] += sm[tid + off];
        __syncthreads();
    }
    if (tid == 0) loss_out[0] = sm[0] * (1.0f / (float)C_CAND);
}

// ============================================================================
// launch
// ============================================================================
extern "C" void kernel_launch(void* const* d_in, const int* in_sizes, int n_in,
                              void* d_out, int out_size) {
    const float* emb    = (const float*)d_in[0];   // [100000, 1024]
    const int*   src    = (const int*)d_in[1];     // [32768]
    const int*   dst    = (const int*)d_in[2];     // [32768]
    const int*   labels = (const int*)d_in[3];     // [32768]
    const float* W1     = (const float*)d_in[4];   // [4096, 1024]
    const float* b1     = (const float*)d_in[5];   // [1024]
    const float* W2     = (const float*)d_in[6];   // [1024, 10]
    const float* b2     = (const float*)d_in[7];   // [10]

    float* out = (float*)d_out;
    float* logits_dst;
    float* loss_dst = nullptr;

    if (out_size >= C_CAND * NREL + 1) {
        loss_dst   = out;
        logits_dst = out + 1;
    } else if (out_size == C_CAND * NREL) {
        logits_dst = out;
    } else {
        void* p = nullptr;
        cudaGetSymbolAddress(&p, g_logits_sink);
        logits_dst = (float*)p;
        loss_dst   = out;
    }

    cudaFuncSetAttribute(gemm1_mma_kernel,
                         cudaFuncAttributeMaxDynamicSharedMemorySize, GEMM_SMEM);

    dim3 gw(K4 / 32, HID / 32);
    wsplit_kernel<<<gw, dim3(32, 8)>>>(W1);

    build_feats_kernel<<<C_CAND, 256>>>(emb, src, dst);

    dim3 gg(HID / BN, C_CAND / BM);    // (8, 256), x = N tile
    gemm1_mma_kernel<<<gg, 256, GEMM_SMEM>>>(b1);

    head_kernel<<<C_CAND / 8, 256>>>(W2, b2, labels, logits_dst);

    if (loss_dst) reduce_loss_kernel<<<1, 1024>>>(loss_dst);
}

// round 11
// speedup vs baseline: 2.3831x; 1.0082x over previous
#include <cuda_runtime.h>
#include <cuda_bf16.h>
#include <cstdint>
#include <math.h>

typedef unsigned long long ull;

#define C_CAND 32768
#define HID    1024
#define K4     4096
#define NREL   10

// ---- scratch (static device globals; no allocations anywhere) ----
__device__ __align__(16) __nv_bfloat16 g_fHi[(size_t)C_CAND * K4];   // 256 MB feats hi
__device__ __align__(16) __nv_bfloat16 g_fLo[(size_t)C_CAND * K4];   // 256 MB feats lo
__device__ __align__(16) __nv_bfloat16 g_wHi[(size_t)HID * K4];      // 8 MB  W1^T hi [n][k]
__device__ __align__(16) __nv_bfloat16 g_wLo[(size_t)HID * K4];      // 8 MB  W1^T lo
__device__ __align__(16) float g_h[(size_t)C_CAND * HID];            // 128 MB
__device__ float g_loss[C_CAND];
__device__ float g_logits_sink[(size_t)C_CAND * NREL];

__device__ __forceinline__ float gelu_exact(float x) {
    return 0.5f * x * (1.0f + erff(x * 0.70710678118654752440f));
}

// ============================ PTX helpers (sm_80+ base-target only) =========
__device__ __forceinline__ uint32_t smem_u32(const void* p) {
    uint32_t a;
    asm("{ .reg .u64 t; cvta.to.shared.u64 t, %1; cvt.u32.u64 %0, t; }" : "=r"(a) : "l"(p));
    return a;
}
__device__ __forceinline__ void cpasync16(uint32_t dst, const void* src) {
    asm volatile("cp.async.cg.shared.global [%0], [%1], 16;" :: "r"(dst), "l"(src));
}
__device__ __forceinline__ void ldsm4(uint32_t& r0, uint32_t& r1, uint32_t& r2,
                                      uint32_t& r3, uint32_t addr) {
    asm volatile("ldmatrix.sync.aligned.m8n8.x4.shared.b16 {%0,%1,%2,%3}, [%4];"
                 : "=r"(r0), "=r"(r1), "=r"(r2), "=r"(r3) : "r"(addr));
}
// NOT volatile: register in/out constraints carry the dependencies; lets ptxas
// schedule independent MMAs between same-accumulator reuses.
__device__ __forceinline__ void mma16816(float* c, const uint32_t* a, const uint32_t* b) {
    asm("mma.sync.aligned.m16n8k16.row.col.f32.bf16.bf16.f32 "
        "{%0,%1,%2,%3}, {%4,%5,%6,%7}, {%8,%9}, {%0,%1,%2,%3};"
        : "+f"(c[0]), "+f"(c[1]), "+f"(c[2]), "+f"(c[3])
        : "r"(a[0]), "r"(a[1]), "r"(a[2]), "r"(a[3]), "r"(b[0]), "r"(b[1]));
}

// ============================================================================
// Kernel 0: transpose + bf16-split W1 -> g_wHi/g_wLo as [N=1024][K=4096]
// ============================================================================
__global__ void wsplit_kernel(const float* __restrict__ W1) {
    __shared__ float sm[32][33];
    const int k0 = blockIdx.x * 32;
    const int n0 = blockIdx.y * 32;
    const int tx = threadIdx.x, ty = threadIdx.y;   // 32 x 8
    #pragma unroll
    for (int i = 0; i < 4; ++i)
        sm[ty + i * 8][tx] = W1[(size_t)(k0 + ty + i * 8) * HID + n0 + tx];
    __syncthreads();
    #pragma unroll
    for (int i = 0; i < 4; ++i) {
        const int n = ty + i * 8;
        const float v = sm[tx][n];                  // = W1[k0+tx][n0+n]
        const __nv_bfloat16 hb = __float2bfloat16_rn(v);
        const float lo = v - __bfloat162float(hb);
        const size_t o = (size_t)(n0 + n) * K4 + k0 + tx;
        g_wHi[o] = hb;
        g_wLo[o] = __float2bfloat16_rn(lo);
    }
}

// ============================================================================
// Kernel 1: gather + build feats, split to bf16 hi/lo   [C, 4H]
// ============================================================================
__device__ __forceinline__ void split_store4(float4 v, size_t elem_off) {
    unsigned short h0 = __bfloat16_as_ushort(__float2bfloat16_rn(v.x));
    unsigned short h1 = __bfloat16_as_ushort(__float2bfloat16_rn(v.y));
    unsigned short h2 = __bfloat16_as_ushort(__float2bfloat16_rn(v.z));
    unsigned short h3 = __bfloat16_as_ushort(__float2bfloat16_rn(v.w));
    float r0 = v.x - __bfloat162float(__ushort_as_bfloat16(h0));
    float r1 = v.y - __bfloat162float(__ushort_as_bfloat16(h1));
    float r2 = v.z - __bfloat162float(__ushort_as_bfloat16(h2));
    float r3 = v.w - __bfloat162float(__ushort_as_bfloat16(h3));
    unsigned short l0 = __bfloat16_as_ushort(__float2bfloat16_rn(r0));
    unsigned short l1 = __bfloat16_as_ushort(__float2bfloat16_rn(r1));
    unsigned short l2 = __bfloat16_as_ushort(__float2bfloat16_rn(r2));
    unsigned short l3 = __bfloat16_as_ushort(__float2bfloat16_rn(r3));
    uint2 hi, lo;
    hi.x = (uint32_t)h0 | ((uint32_t)h1 << 16);
    hi.y = (uint32_t)h2 | ((uint32_t)h3 << 16);
    lo.x = (uint32_t)l0 | ((uint32_t)l1 << 16);
    lo.y = (uint32_t)l2 | ((uint32_t)l3 << 16);
    *(uint2*)(g_fHi + elem_off) = hi;
    *(uint2*)(g_fLo + elem_off) = lo;
}

__global__ void build_feats_kernel(const float* __restrict__ emb,
                                   const int* __restrict__ src_idx,
                                   const int* __restrict__ dst_idx) {
    const int c = blockIdx.x;
    const int h = threadIdx.x << 2;                 // 0..1020
    const int si = src_idx[c];
    const int di = dst_idx[c];

    const float4 s = *(const float4*)(emb + (size_t)si * HID + h);
    const float4 d = *(const float4*)(emb + (size_t)di * HID + h);

    float4 ad, pd;
    ad.x = fabsf(s.x - d.x); ad.y = fabsf(s.y - d.y);
    ad.z = fabsf(s.z - d.z); ad.w = fabsf(s.w - d.w);
    pd.x = s.x * d.x; pd.y = s.y * d.y; pd.z = s.z * d.z; pd.w = s.w * d.w;

    const size_t base = (size_t)c * K4;
    split_store4(s,  base + h);
    split_store4(d,  base + HID + h);
    split_store4(ad, base + 2 * HID + h);
    split_store4(pd, base + 3 * HID + h);
}

// ============================================================================
// Kernel 2: h = gelu(feats @ W1 + b1) via mma.sync bf16 3-product emulation
// CTA tile 128x128, Kc=32, 3-stage cp.async pipe, 2 CTAs/SM.
// Inner loop restructured into 3 passes (HH, HL, LH) over 8 distinct
// accumulators -> same-accumulator MMA reuse distance = 8 (no RAW bubbles),
// and MMA asm is non-volatile so ptxas can interleave freely.
// ============================================================================
#define BM          128
#define BN          128
#define BK          32
#define NSTAGE      3
#define STG_BYTES   32768    // Ahi 8K | Alo 8K | Bhi 8K | Blo 8K
#define OFF_AHI     0
#define OFF_ALO     8192
#define OFF_BHI     16384
#define OFF_BLO     24576
#define GEMM_SMEM   (NSTAGE * STG_BYTES)

__device__ __forceinline__ void load_stage(int t, int slot, int tid, int m0, int n0,
                                           uint32_t sb) {
    const int k0 = t * BK;
    const uint32_t st = sb + slot * STG_BYTES;
    #pragma unroll
    for (int i = 0; i < 2; ++i) {
        const int idx = i * 256 + tid;         // 0..511
        const int r = idx >> 2;                // row 0..127
        const int c = idx & 3;                 // 16B chunk 0..3
        const uint32_t d = st + r * 64 + ((c ^ ((r >> 1) & 3)) << 4);
        const size_t goA = (size_t)(m0 + r) * K4 + k0 + c * 8;
        const size_t goB = (size_t)(n0 + r) * K4 + k0 + c * 8;
        cpasync16(d + OFF_AHI, g_fHi + goA);
        cpasync16(d + OFF_ALO, g_fLo + goA);
        cpasync16(d + OFF_BHI, g_wHi + goB);
        cpasync16(d + OFF_BLO, g_wLo + goB);
    }
}

__global__ void __launch_bounds__(256, 2)
gemm1_mma_kernel(const float* __restrict__ b1) {
    extern __shared__ __align__(128) char smem[];
    const uint32_t sb = smem_u32(smem);
    const int tid  = threadIdx.x;
    const int lane = tid & 31;
    const int wrp  = tid >> 5;
    const int n0 = blockIdx.x * BN;      // x fastest: N tiles of one M block co-run
    const int m0 = blockIdx.y * BM;

    const int m_off = (wrp & 3) * 32;    // warp M origin
    const int n_off = (wrp >> 2) * 64;   // warp N origin

    const int l15 = lane & 15;
    const int lhf = lane >> 4;           // 0/1: 16B chunk within 16-col block

    uint32_t rAb[2], rBb[4];
    uint32_t rAs[2], rBs[4];
    #pragma unroll
    for (int mt = 0; mt < 2; ++mt) {
        const int r = m_off + mt * 16 + l15;
        rAb[mt] = (uint32_t)r * 64;
        rAs[mt] = (uint32_t)((r >> 1) & 3);
    }
    #pragma unroll
    for (int nt = 0; nt < 4; ++nt) {
        const int r = n_off + nt * 16 + l15;
        rBb[nt] = (uint32_t)r * 64;
        rBs[nt] = (uint32_t)((r >> 1) & 3);
    }

    float acc[2][8][4];
    #pragma unroll
    for (int mt = 0; mt < 2; ++mt)
        #pragma unroll
        for (int j = 0; j < 8; ++j)
            #pragma unroll
            for (int q = 0; q < 4; ++q) acc[mt][j][q] = 0.0f;

    load_stage(0, 0, tid, m0, n0, sb);
    asm volatile("cp.async.commit_group;" ::: "memory");
    load_stage(1, 1, tid, m0, n0, sb);
    asm volatile("cp.async.commit_group;" ::: "memory");

    const int NT = K4 / BK;   // 128
    int slot = 0, nslot = 2;
    for (int t = 0; t < NT; ++t) {
        asm volatile("cp.async.wait_group 1;" ::: "memory");
        __syncthreads();

        if (t + 2 < NT) load_stage(t + 2, nslot, tid, m0, n0, sb);
        asm volatile("cp.async.commit_group;" ::: "memory");

        const uint32_t st = sb + slot * STG_BYTES;
        #pragma unroll
        for (int kk = 0; kk < 2; ++kk) {
            const uint32_t ck = (uint32_t)(kk * 2 + lhf);
            uint32_t aH[2][4], aL[2][4];
            #pragma unroll
            for (int mt = 0; mt < 2; ++mt) {
                const uint32_t ao = rAb[mt] + ((ck ^ rAs[mt]) << 4);
                ldsm4(aH[mt][0], aH[mt][1], aH[mt][2], aH[mt][3], st + OFF_AHI + ao);
                ldsm4(aL[mt][0], aL[mt][1], aL[mt][2], aL[mt][3], st + OFF_ALO + ao);
            }
            #pragma unroll
            for (int g = 0; g < 2; ++g) {          // pairs of nt tiles
                uint32_t bH[2][2][2], bL[2][2][2]; // [ntl][u][reg]
                #pragma unroll
                for (int ntl = 0; ntl < 2; ++ntl) {
                    const int nt = 2 * g + ntl;
                    const uint32_t bo = rBb[nt] + ((ck ^ rBs[nt]) << 4);
                    uint32_t r0, r1, r2, r3;
                    ldsm4(r0, r1, r2, r3, st + OFF_BHI + bo);
                    bH[ntl][0][0] = r0; bH[ntl][0][1] = r2;
                    bH[ntl][1][0] = r1; bH[ntl][1][1] = r3;
                    ldsm4(r0, r1, r2, r3, st + OFF_BLO + bo);
                    bL[ntl][0][0] = r0; bL[ntl][0][1] = r2;
                    bL[ntl][1][0] = r1; bL[ntl][1][1] = r3;
                }
                // pass 1: aH x bH  (8 distinct accumulators)
                #pragma unroll
                for (int mt = 0; mt < 2; ++mt)
                    #pragma unroll
                    for (int ntl = 0; ntl < 2; ++ntl)
                        #pragma unroll
                        for (int u = 0; u < 2; ++u)
                            mma16816(acc[mt][2 * (2 * g + ntl) + u], aH[mt], bH[ntl][u]);
                // pass 2: aH x bL
                #pragma unroll
                for (int mt = 0; mt < 2; ++mt)
                    #pragma unroll
                    for (int ntl = 0; ntl < 2; ++ntl)
                        #pragma unroll
                        for (int u = 0; u < 2; ++u)
                            mma16816(acc[mt][2 * (2 * g + ntl) + u], aH[mt], bL[ntl][u]);
                // pass 3: aL x bH
                #pragma unroll
                for (int mt = 0; mt < 2; ++mt)
                    #pragma unroll
                    for (int ntl = 0; ntl < 2; ++ntl)
                        #pragma unroll
                        for (int u = 0; u < 2; ++u)
                            mma16816(acc[mt][2 * (2 * g + ntl) + u], aL[mt], bH[ntl][u]);
            }
        }

        slot = slot + 1 == NSTAGE ? 0 : slot + 1;
        nslot = nslot + 1 == NSTAGE ? 0 : nslot + 1;
    }

    // epilogue: + bias, exact GELU, direct global stores (float2)
    const int mrow = m0 + m_off + (lane >> 2);
    const int col0 = n0 + n_off + 2 * (lane & 3);
    #pragma unroll
    for (int mt = 0; mt < 2; ++mt) {
        const int r = mrow + mt * 16;
        #pragma unroll
        for (int j = 0; j < 8; ++j) {
            const int c = col0 + j * 8;
            const float bb0 = __ldg(b1 + c);
            const float bb1 = __ldg(b1 + c + 1);
            float2 v0, v1;
            v0.x = gelu_exact(acc[mt][j][0] + bb0);
            v0.y = gelu_exact(acc[mt][j][1] + bb1);
            v1.x = gelu_exact(acc[mt][j][2] + bb0);
            v1.y = gelu_exact(acc[mt][j][3] + bb1);
            *(float2*)(g_h + (size_t)r * HID + c)       = v0;
            *(float2*)(g_h + (size_t)(r + 8) * HID + c) = v1;
        }
    }
}

// ============================================================================
// Kernel 3: logits = h @ W2 + b2 ; log-softmax ; NLL
// 4 candidates per warp SHARING each Wt float4 read -> LDS traffic /4.
// ~80 live regs (40 acc + 16 h + 4 w).
// ============================================================================
__global__ __launch_bounds__(256)
void head_kernel(const float* __restrict__ W2, const float* __restrict__ b2,
                 const int* __restrict__ labels, float* __restrict__ logits_out) {
    __shared__ float Wt[NREL][HID];   // 40 KB

    const int tid = threadIdx.x;
    for (int i = tid; i < NREL * HID; i += 256) {
        const int k = i / NREL;
        const int r = i - k * NREL;
        Wt[r][k] = W2[i];
    }
    __syncthreads();

    const int warp = tid >> 5;
    const int lane = tid & 31;
    const int c0 = blockIdx.x * 32 + warp * 4;

    const float* h0 = g_h + (size_t)(c0 + 0) * HID;
    const float* h1 = g_h + (size_t)(c0 + 1) * HID;
    const float* h2 = g_h + (size_t)(c0 + 2) * HID;
    const float* h3 = g_h + (size_t)(c0 + 3) * HID;

    float acc0[NREL], acc1[NREL], acc2[NREL], acc3[NREL];
    #pragma unroll
    for (int r = 0; r < NREL; ++r) { acc0[r] = 0.f; acc1[r] = 0.f; acc2[r] = 0.f; acc3[r] = 0.f; }

    #pragma unroll
    for (int i = 0; i < 8; ++i) {
        const int k = (i * 32 + lane) * 4;      // float4 index, coalesced
        const float4 a0 = *(const float4*)(h0 + k);
        const float4 a1 = *(const float4*)(h1 + k);
        const float4 a2 = *(const float4*)(h2 + k);
        const float4 a3 = *(const float4*)(h3 + k);
        #pragma unroll
        for (int r = 0; r < NREL; ++r) {
            const float4 w = *(const float4*)&Wt[r][k];   // broadcast, read ONCE
            acc0[r] += a0.x * w.x + a0.y * w.y + a0.z * w.z + a0.w * w.w;
            acc1[r] += a1.x * w.x + a1.y * w.y + a1.z * w.z + a1.w * w.w;
            acc2[r] += a2.x * w.x + a2.y * w.y + a2.z * w.z + a2.w * w.w;
            acc3[r] += a3.x * w.x + a3.y * w.y + a3.z * w.z + a3.w * w.w;
        }
    }

    #pragma unroll
    for (int r = 0; r < NREL; ++r) {
        #pragma unroll
        for (int off = 16; off > 0; off >>= 1) {
            acc0[r] += __shfl_down_sync(0xffffffffu, acc0[r], off);
            acc1[r] += __shfl_down_sync(0xffffffffu, acc1[r], off);
            acc2[r] += __shfl_down_sync(0xffffffffu, acc2[r], off);
            acc3[r] += __shfl_down_sync(0xffffffffu, acc3[r], off);
        }
    }

    if (lane == 0) {
        float* accs[4] = { acc0, acc1, acc2, acc3 };
        #pragma unroll
        for (int cc = 0; cc < 4; ++cc) {
            const int c = c0 + cc;
            float lg[NREL];
            float mx = -1e30f;
            #pragma unroll
            for (int r = 0; r < NREL; ++r) {
                lg[r] = accs[cc][r] + b2[r];
                mx = fmaxf(mx, lg[r]);
            }
            float s = 0.0f;
            #pragma unroll
            for (int r = 0; r < NREL; ++r) s += expf(lg[r] - mx);
            const float lse = logf(s) + mx;

            const int lbl = labels[c];
            g_loss[c] = lse - lg[lbl];

            float* dst = logits_out + (size_t)c * NREL;
            #pragma unroll
            for (int r = 0; r < NREL; ++r) dst[r] = lg[r];
        }
    }
}

// ============================================================================
// Kernel 4: loss = mean(g_loss)  -- single block, fixed-order tree
// ============================================================================
__global__ void reduce_loss_kernel(float* __restrict__ loss_out) {
    __shared__ float sm[1024];
    const int tid = threadIdx.x;
    float s = 0.0f;
    #pragma unroll
    for (int i = 0; i < 32; ++i) s += g_loss[tid + (i << 10)];
    sm[tid] = s;
    __syncthreads();
    for (int off = 512; off > 0; off >>= 1) {
        if (tid < off) sm[tid] += sm[tid + off];
        __syncthreads();
    }
    if (tid == 0) loss_out[0] = sm[0] * (1.0f / (float)C_CAND);
}

// ============================================================================
// launch
// ============================================================================
extern "C" void kernel_launch(void* const* d_in, const int* in_sizes, int n_in,
                              void* d_out, int out_size) {
    const float* emb    = (const float*)d_in[0];   // [100000, 1024]
    const int*   src    = (const int*)d_in[1];     // [32768]
    const int*   dst    = (const int*)d_in[2];     // [32768]
    const int*   labels = (const int*)d_in[3];     // [32768]
    const float* W1     = (const float*)d_in[4];   // [4096, 1024]
    const float* b1     = (const float*)d_in[5];   // [1024]
    const float* W2     = (const float*)d_in[6];   // [1024, 10]
    const float* b2     = (const float*)d_in[7];   // [10]

    float* out = (float*)d_out;
    float* logits_dst;
    float* loss_dst = nullptr;

    if (out_size >= C_CAND * NREL + 1) {
        loss_dst   = out;
        logits_dst = out + 1;
    } else if (out_size == C_CAND * NREL) {
        logits_dst = out;
    } else {
        void* p = nullptr;
        cudaGetSymbolAddress(&p, g_logits_sink);
        logits_dst = (float*)p;
        loss_dst   = out;
    }

    cudaFuncSetAttribute(gemm1_mma_kernel,
                         cudaFuncAttributeMaxDynamicSharedMemorySize, GEMM_SMEM);

    dim3 gw(K4 / 32, HID / 32);
    wsplit_kernel<<<gw, dim3(32, 8)>>>(W1);

    build_feats_kernel<<<C_CAND, 256>>>(emb, src, dst);

    dim3 gg(HID / BN, C_CAND / BM);    // (8, 256), x = N tile
    gemm1_mma_kernel<<<gg, 256, GEMM_SMEM>>>(b1);

    head_kernel<<<C_CAND / 32, 256>>>(W2, b2, labels, logits_dst);

    if (loss_dst) reduce_loss_kernel<<<1, 1024>>>(loss_dst);
}

// round 12
// speedup vs baseline: 3.4445x; 1.4454x over previous
#include <cuda_runtime.h>
#include <cuda_fp16.h>
#include <cstdint>
#include <math.h>

typedef unsigned long long ull;

#define C_CAND 32768
#define HID    1024
#define K4     4096
#define NREL   10

// ---- scratch (static device globals; no allocations anywhere) ----
__device__ __align__(16) __half g_fA[(size_t)C_CAND * K4];    // 256 MB feats fp16
__device__ __align__(16) __half g_wHi[(size_t)HID * K4];      // 8 MB  W1^T hi [n][k]
__device__ __align__(16) __half g_wLo[(size_t)HID * K4];      // 8 MB  W1^T lo
__device__ __align__(16) float g_h[(size_t)C_CAND * HID];     // 128 MB
__device__ float g_loss[C_CAND];
__device__ float g_logits_sink[(size_t)C_CAND * NREL];

__device__ __forceinline__ float gelu_exact(float x) {
    return 0.5f * x * (1.0f + erff(x * 0.70710678118654752440f));
}

// ============================ PTX helpers (sm_80+ base-target only) =========
__device__ __forceinline__ uint32_t smem_u32(const void* p) {
    uint32_t a;
    asm("{ .reg .u64 t; cvta.to.shared.u64 t, %1; cvt.u32.u64 %0, t; }" : "=r"(a) : "l"(p));
    return a;
}
__device__ __forceinline__ void cpasync16(uint32_t dst, const void* src) {
    asm volatile("cp.async.cg.shared.global [%0], [%1], 16;" :: "r"(dst), "l"(src));
}
__device__ __forceinline__ void ldsm4(uint32_t& r0, uint32_t& r1, uint32_t& r2,
                                      uint32_t& r3, uint32_t addr) {
    asm volatile("ldmatrix.sync.aligned.m8n8.x4.shared.b16 {%0,%1,%2,%3}, [%4];"
                 : "=r"(r0), "=r"(r1), "=r"(r2), "=r"(r3) : "r"(addr));
}
// fp16 MMA, fp32 accumulate. NOT volatile: deps carried by constraints.
__device__ __forceinline__ void mma16816h(float* c, const uint32_t* a, const uint32_t* b) {
    asm("mma.sync.aligned.m16n8k16.row.col.f32.f16.f16.f32 "
        "{%0,%1,%2,%3}, {%4,%5,%6,%7}, {%8,%9}, {%0,%1,%2,%3};"
        : "+f"(c[0]), "+f"(c[1]), "+f"(c[2]), "+f"(c[3])
        : "r"(a[0]), "r"(a[1]), "r"(a[2]), "r"(a[3]), "r"(b[0]), "r"(b[1]));
}

// ============================================================================
// Kernel 0: transpose + fp16-split W1 -> g_wHi/g_wLo as [N=1024][K=4096]
// B = Bhi + Blo captures 22 mantissa bits -> B effectively exact.
// ============================================================================
__global__ void wsplit_kernel(const float* __restrict__ W1) {
    __shared__ float sm[32][33];
    const int k0 = blockIdx.x * 32;
    const int n0 = blockIdx.y * 32;
    const int tx = threadIdx.x, ty = threadIdx.y;   // 32 x 8
    #pragma unroll
    for (int i = 0; i < 4; ++i)
        sm[ty + i * 8][tx] = W1[(size_t)(k0 + ty + i * 8) * HID + n0 + tx];
    __syncthreads();
    #pragma unroll
    for (int i = 0; i < 4; ++i) {
        const int n = ty + i * 8;
        const float v = sm[tx][n];                  // = W1[k0+tx][n0+n]
        const __half hb = __float2half_rn(v);
        const float lo = v - __half2float(hb);
        const size_t o = (size_t)(n0 + n) * K4 + k0 + tx;
        g_wHi[o] = hb;
        g_wLo[o] = __float2half_rn(lo);
    }
}

// ============================================================================
// Kernel 1: gather + build feats as single fp16   [C, 4H]
// ============================================================================
__device__ __forceinline__ void store_half4(float4 v, size_t elem_off) {
    unsigned short h0 = __half_as_ushort(__float2half_rn(v.x));
    unsigned short h1 = __half_as_ushort(__float2half_rn(v.y));
    unsigned short h2 = __half_as_ushort(__float2half_rn(v.z));
    unsigned short h3 = __half_as_ushort(__float2half_rn(v.w));
    uint2 p;
    p.x = (uint32_t)h0 | ((uint32_t)h1 << 16);
    p.y = (uint32_t)h2 | ((uint32_t)h3 << 16);
    *(uint2*)(g_fA + elem_off) = p;
}

__global__ void build_feats_kernel(const float* __restrict__ emb,
                                   const int* __restrict__ src_idx,
                                   const int* __restrict__ dst_idx) {
    const int c = blockIdx.x;
    const int h = threadIdx.x << 2;                 // 0..1020
    const int si = src_idx[c];
    const int di = dst_idx[c];

    const float4 s = *(const float4*)(emb + (size_t)si * HID + h);
    const float4 d = *(const float4*)(emb + (size_t)di * HID + h);

    float4 ad, pd;
    ad.x = fabsf(s.x - d.x); ad.y = fabsf(s.y - d.y);
    ad.z = fabsf(s.z - d.z); ad.w = fabsf(s.w - d.w);
    pd.x = s.x * d.x; pd.y = s.y * d.y; pd.z = s.z * d.z; pd.w = s.w * d.w;

    const size_t base = (size_t)c * K4;
    store_half4(s,  base + h);
    store_half4(d,  base + HID + h);
    store_half4(ad, base + 2 * HID + h);
    store_half4(pd, base + 3 * HID + h);
}

// ============================================================================
// Kernel 2: h = gelu(feats @ W1 + b1) via fp16 2-product emulation:
//   A_fp16 · Bhi + A_fp16 · Blo   (B exact to 22 bits; error = A rounding)
// CTA tile 128x128, Kc=32, 4-stage cp.async pipe (24KB/stage, 96KB/CTA),
// 2 CTAs/SM. 8 warps as 4(M)x2(N); warp tile 32x64.
// Per k16 per warp: 10 LDSM.x4, 16 HMMA.
// ============================================================================
#define BM          128
#define BN          128
#define BK          32
#define NSTAGE      4
#define STG_BYTES   24576    // A 8K | Bhi 8K | Blo 8K
#define OFF_A       0
#define OFF_BHI     8192
#define OFF_BLO     16384
#define GEMM_SMEM   (NSTAGE * STG_BYTES)

__device__ __forceinline__ void load_stage(int t, int slot, int tid, int m0, int n0,
                                           uint32_t sb) {
    const int k0 = t * BK;
    const uint32_t st = sb + slot * STG_BYTES;
    #pragma unroll
    for (int i = 0; i < 2; ++i) {
        const int idx = i * 256 + tid;         // 0..511
        const int r = idx >> 2;                // row 0..127
        const int c = idx & 3;                 // 16B chunk 0..3
        const uint32_t d = st + r * 64 + ((c ^ ((r >> 1) & 3)) << 4);
        const size_t goA = (size_t)(m0 + r) * K4 + k0 + c * 8;
        const size_t goB = (size_t)(n0 + r) * K4 + k0 + c * 8;
        cpasync16(d + OFF_A,   g_fA  + goA);
        cpasync16(d + OFF_BHI, g_wHi + goB);
        cpasync16(d + OFF_BLO, g_wLo + goB);
    }
}

__global__ void __launch_bounds__(256, 2)
gemm1_mma_kernel(const float* __restrict__ b1) {
    extern __shared__ __align__(128) char smem[];
    const uint32_t sb = smem_u32(smem);
    const int tid  = threadIdx.x;
    const int lane = tid & 31;
    const int wrp  = tid >> 5;
    const int n0 = blockIdx.x * BN;      // x fastest: N tiles of one M block co-run
    const int m0 = blockIdx.y * BM;

    const int m_off = (wrp & 3) * 32;    // warp M origin
    const int n_off = (wrp >> 2) * 64;   // warp N origin

    const int l15 = lane & 15;
    const int lhf = lane >> 4;           // 0/1: 16B chunk within 16-col block

    uint32_t rAb[2], rBb[4];
    uint32_t rAs[2], rBs[4];
    #pragma unroll
    for (int mt = 0; mt < 2; ++mt) {
        const int r = m_off + mt * 16 + l15;
        rAb[mt] = (uint32_t)r * 64;
        rAs[mt] = (uint32_t)((r >> 1) & 3);
    }
    #pragma unroll
    for (int nt = 0; nt < 4; ++nt) {
        const int r = n_off + nt * 16 + l15;
        rBb[nt] = (uint32_t)r * 64;
        rBs[nt] = (uint32_t)((r >> 1) & 3);
    }

    float acc[2][8][4];
    #pragma unroll
    for (int mt = 0; mt < 2; ++mt)
        #pragma unroll
        for (int j = 0; j < 8; ++j)
            #pragma unroll
            for (int q = 0; q < 4; ++q) acc[mt][j][q] = 0.0f;

    load_stage(0, 0, tid, m0, n0, sb);
    asm volatile("cp.async.commit_group;" ::: "memory");
    load_stage(1, 1, tid, m0, n0, sb);
    asm volatile("cp.async.commit_group;" ::: "memory");
    load_stage(2, 2, tid, m0, n0, sb);
    asm volatile("cp.async.commit_group;" ::: "memory");

    const int NT = K4 / BK;   // 128
    for (int t = 0; t < NT; ++t) {
        const int slot = t & 3;
        asm volatile("cp.async.wait_group 2;" ::: "memory");
        __syncthreads();

        if (t + 3 < NT) load_stage(t + 3, (t + 3) & 3, tid, m0, n0, sb);
        asm volatile("cp.async.commit_group;" ::: "memory");

        const uint32_t st = sb + slot * STG_BYTES;
        #pragma unroll
        for (int kk = 0; kk < 2; ++kk) {
            const uint32_t ck = (uint32_t)(kk * 2 + lhf);
            uint32_t aF[2][4];
            #pragma unroll
            for (int mt = 0; mt < 2; ++mt) {
                const uint32_t ao = rAb[mt] + ((ck ^ rAs[mt]) << 4);
                ldsm4(aF[mt][0], aF[mt][1], aF[mt][2], aF[mt][3], st + OFF_A + ao);
            }
            #pragma unroll
            for (int g = 0; g < 2; ++g) {          // pairs of nt tiles
                uint32_t bH[2][2][2], bL[2][2][2]; // [ntl][u][reg]
                #pragma unroll
                for (int ntl = 0; ntl < 2; ++ntl) {
                    const int nt = 2 * g + ntl;
                    const uint32_t bo = rBb[nt] + ((ck ^ rBs[nt]) << 4);
                    uint32_t r0, r1, r2, r3;
                    ldsm4(r0, r1, r2, r3, st + OFF_BHI + bo);
                    bH[ntl][0][0] = r0; bH[ntl][0][1] = r2;
                    bH[ntl][1][0] = r1; bH[ntl][1][1] = r3;
                    ldsm4(r0, r1, r2, r3, st + OFF_BLO + bo);
                    bL[ntl][0][0] = r0; bL[ntl][0][1] = r2;
                    bL[ntl][1][0] = r1; bL[ntl][1][1] = r3;
                }
                // pass 1: A x Bhi  (8 distinct accumulators)
                #pragma unroll
                for (int mt = 0; mt < 2; ++mt)
                    #pragma unroll
                    for (int ntl = 0; ntl < 2; ++ntl)
                        #pragma unroll
                        for (int u = 0; u < 2; ++u)
                            mma16816h(acc[mt][2 * (2 * g + ntl) + u], aF[mt], bH[ntl][u]);
                // pass 2: A x Blo
                #pragma unroll
                for (int mt = 0; mt < 2; ++mt)
                    #pragma unroll
                    for (int ntl = 0; ntl < 2; ++ntl)
                        #pragma unroll
                        for (int u = 0; u < 2; ++u)
                            mma16816h(acc[mt][2 * (2 * g + ntl) + u], aF[mt], bL[ntl][u]);
            }
        }
    }

    // epilogue: + bias, exact GELU, direct global stores (float2)
    const int mrow = m0 + m_off + (lane >> 2);
    const int col0 = n0 + n_off + 2 * (lane & 3);
    #pragma unroll
    for (int mt = 0; mt < 2; ++mt) {
        const int r = mrow + mt * 16;
        #pragma unroll
        for (int j = 0; j < 8; ++j) {
            const int c = col0 + j * 8;
            const float bb0 = __ldg(b1 + c);
            const float bb1 = __ldg(b1 + c + 1);
            float2 v0, v1;
            v0.x = gelu_exact(acc[mt][j][0] + bb0);
            v0.y = gelu_exact(acc[mt][j][1] + bb1);
            v1.x = gelu_exact(acc[mt][j][2] + bb0);
            v1.y = gelu_exact(acc[mt][j][3] + bb1);
            *(float2*)(g_h + (size_t)r * HID + c)       = v0;
            *(float2*)(g_h + (size_t)(r + 8) * HID + c) = v1;
        }
    }
}

// ============================================================================
// Kernel 3: logits = h @ W2 + b2 ; log-softmax ; NLL
// 4 candidates per warp sharing each Wt float4 read.
// ============================================================================
__global__ __launch_bounds__(256)
void head_kernel(const float* __restrict__ W2, const float* __restrict__ b2,
                 const int* __restrict__ labels, float* __restrict__ logits_out) {
    __shared__ float Wt[NREL][HID];   // 40 KB

    const int tid = threadIdx.x;
    for (int i = tid; i < NREL * HID; i += 256) {
        const int k = i / NREL;
        const int r = i - k * NREL;
        Wt[r][k] = W2[i];
    }
    __syncthreads();

    const int warp = tid >> 5;
    const int lane = tid & 31;
    const int c0 = blockIdx.x * 32 + warp * 4;

    const float* h0 = g_h + (size_t)(c0 + 0) * HID;
    const float* h1 = g_h + (size_t)(c0 + 1) * HID;
    const float* h2 = g_h + (size_t)(c0 + 2) * HID;
    const float* h3 = g_h + (size_t)(c0 + 3) * HID;

    float acc0[NREL], acc1[NREL], acc2[NREL], acc3[NREL];
    #pragma unroll
    for (int r = 0; r < NREL; ++r) { acc0[r] = 0.f; acc1[r] = 0.f; acc2[r] = 0.f; acc3[r] = 0.f; }

    #pragma unroll
    for (int i = 0; i < 8; ++i) {
        const int k = (i * 32 + lane) * 4;      // float4 index, coalesced
        const float4 a0 = *(const float4*)(h0 + k);
        const float4 a1 = *(const float4*)(h1 + k);
        const float4 a2 = *(const float4*)(h2 + k);
        const float4 a3 = *(const float4*)(h3 + k);
        #pragma unroll
        for (int r = 0; r < NREL; ++r) {
            const float4 w = *(const float4*)&Wt[r][k];   // broadcast, read ONCE
            acc0[r] += a0.x * w.x + a0.y * w.y + a0.z * w.z + a0.w * w.w;
            acc1[r] += a1.x * w.x + a1.y * w.y + a1.z * w.z + a1.w * w.w;
            acc2[r] += a2.x * w.x + a2.y * w.y + a2.z * w.z + a2.w * w.w;
            acc3[r] += a3.x * w.x + a3.y * w.y + a3.z * w.z + a3.w * w.w;
        }
    }

    #pragma unroll
    for (int r = 0; r < NREL; ++r) {
        #pragma unroll
        for (int off = 16; off > 0; off >>= 1) {
            acc0[r] += __shfl_down_sync(0xffffffffu, acc0[r], off);
            acc1[r] += __shfl_down_sync(0xffffffffu, acc1[r], off);
            acc2[r] += __shfl_down_sync(0xffffffffu, acc2[r], off);
            acc3[r] += __shfl_down_sync(0xffffffffu, acc3[r], off);
        }
    }

    if (lane == 0) {
        float* accs[4] = { acc0, acc1, acc2, acc3 };
        #pragma unroll
        for (int cc = 0; cc < 4; ++cc) {
            const int c = c0 + cc;
            float lg[NREL];
            float mx = -1e30f;
            #pragma unroll
            for (int r = 0; r < NREL; ++r) {
                lg[r] = accs[cc][r] + b2[r];
                mx = fmaxf(mx, lg[r]);
            }
            float s = 0.0f;
            #pragma unroll
            for (int r = 0; r < NREL; ++r) s += expf(lg[r] - mx);
            const float lse = logf(s) + mx;

            const int lbl = labels[c];
            g_loss[c] = lse - lg[lbl];

            float* dst = logits_out + (size_t)c * NREL;
            #pragma unroll
            for (int r = 0; r < NREL; ++r) dst[r] = lg[r];
        }
    }
}

// ============================================================================
// Kernel 4: loss = mean(g_loss)  -- single block, fixed-order tree
// ============================================================================
__global__ void reduce_loss_kernel(float* __restrict__ loss_out) {
    __shared__ float sm[1024];
    const int tid = threadIdx.x;
    float s = 0.0f;
    #pragma unroll
    for (int i = 0; i < 32; ++i) s += g_loss[tid + (i << 10)];
    sm[tid] = s;
    __syncthreads();
    for (int off = 512; off > 0; off >>= 1) {
        if (tid < off) sm[tid] += sm[tid + off];
        __syncthreads();
    }
    if (tid == 0) loss_out[0] = sm[0] * (1.0f / (float)C_CAND);
}

// ============================================================================
// launch
// ============================================================================
extern "C" void kernel_launch(void* const* d_in, const int* in_sizes, int n_in,
                              void* d_out, int out_size) {
    const float* emb    = (const float*)d_in[0];   // [100000, 1024]
    const int*   src    = (const int*)d_in[1];     // [32768]
    const int*   dst    = (const int*)d_in[2];     // [32768]
    const int*   labels = (const int*)d_in[3];     // [32768]
    const float* W1     = (const float*)d_in[4];   // [4096, 1024]
    const float* b1     = (const float*)d_in[5];   // [1024]
    const float* W2     = (const float*)d_in[6];   // [1024, 10]
    const float* b2     = (const float*)d_in[7];   // [10]

    float* out = (float*)d_out;
    float* logits_dst;
    float* loss_dst = nullptr;

    if (out_size >= C_CAND * NREL + 1) {
        loss_dst   = out;
        logits_dst = out + 1;
    } else if (out_size == C_CAND * NREL) {
        logits_dst = out;
    } else {
        void* p = nullptr;
        cudaGetSymbolAddress(&p, g_logits_sink);
        logits_dst = (float*)p;
        loss_dst   = out;
    }

    cudaFuncSetAttribute(gemm1_mma_kernel,
                         cudaFuncAttributeMaxDynamicSharedMemorySize, GEMM_SMEM);

    dim3 gw(K4 / 32, HID / 32);
    wsplit_kernel<<<gw, dim3(32, 8)>>>(W1);

    build_feats_kernel<<<C_CAND, 256>>>(emb, src, dst);

    dim3 gg(HID / BN, C_CAND / BM);    // (8, 256), x = N tile
    gemm1_mma_kernel<<<gg, 256, GEMM_SMEM>>>(b1);

    head_kernel<<<C_CAND / 32, 256>>>(W2, b2, labels, logits_dst);

    if (loss_dst) reduce_loss_kernel<<<1, 1024>>>(loss_dst);
}

// round 17
// speedup vs baseline: 5.8672x; 1.7034x over previous
#include <cuda_runtime.h>
#include <cuda_fp16.h>
#include <cstdint>
#include <math.h>

typedef unsigned long long ull;

#define C_CAND 32768
#define HID    1024
#define K4     4096
#define NREL   10

// ---- scratch (static device globals; no allocations anywhere) ----
__device__ __align__(16) __half g_fA[(size_t)C_CAND * K4];    // 256 MB feats fp16
__device__ __align__(16) __half g_wF[(size_t)HID * K4];       // 8 MB  W1^T fp16 [n][k]
__device__ __align__(16) float g_h[(size_t)C_CAND * HID];     // 128 MB
__device__ float g_loss[C_CAND];
__device__ float g_logits_sink[(size_t)C_CAND * NREL];

__device__ __forceinline__ float gelu_exact(float x) {
    return 0.5f * x * (1.0f + erff(x * 0.70710678118654752440f));
}

// ============================ PTX helpers (sm_80+ base-target only) =========
__device__ __forceinline__ uint32_t smem_u32(const void* p) {
    uint32_t a;
    asm("{ .reg .u64 t; cvta.to.shared.u64 t, %1; cvt.u32.u64 %0, t; }" : "=r"(a) : "l"(p));
    return a;
}
__device__ __forceinline__ void cpasync16(uint32_t dst, const void* src) {
    asm volatile("cp.async.cg.shared.global [%0], [%1], 16;" :: "r"(dst), "l"(src));
}
__device__ __forceinline__ void ldsm4(uint32_t& r0, uint32_t& r1, uint32_t& r2,
                                      uint32_t& r3, uint32_t addr) {
    asm volatile("ldmatrix.sync.aligned.m8n8.x4.shared.b16 {%0,%1,%2,%3}, [%4];"
                 : "=r"(r0), "=r"(r1), "=r"(r2), "=r"(r3) : "r"(addr));
}
// fp16 MMA, fp32 accumulate. NOT volatile: deps carried by constraints.
__device__ __forceinline__ void mma16816h(float* c, const uint32_t* a, const uint32_t* b) {
    asm("mma.sync.aligned.m16n8k16.row.col.f32.f16.f16.f32 "
        "{%0,%1,%2,%3}, {%4,%5,%6,%7}, {%8,%9}, {%0,%1,%2,%3};"
        : "+f"(c[0]), "+f"(c[1]), "+f"(c[2]), "+f"(c[3])
        : "r"(a[0]), "r"(a[1]), "r"(a[2]), "r"(a[3]), "r"(b[0]), "r"(b[1]));
}

// ============================================================================
// Kernel 0: transpose W1 to fp16 -> g_wF as [N=1024][K=4096]
// ============================================================================
__global__ void wsplit_kernel(const float* __restrict__ W1) {
    __shared__ float sm[32][33];
    const int k0 = blockIdx.x * 32;
    const int n0 = blockIdx.y * 32;
    const int tx = threadIdx.x, ty = threadIdx.y;   // 32 x 8
    #pragma unroll
    for (int i = 0; i < 4; ++i)
        sm[ty + i * 8][tx] = W1[(size_t)(k0 + ty + i * 8) * HID + n0 + tx];
    __syncthreads();
    #pragma unroll
    for (int i = 0; i < 4; ++i) {
        const int n = ty + i * 8;
        const float v = sm[tx][n];                  // = W1[k0+tx][n0+n]
        g_wF[(size_t)(n0 + n) * K4 + k0 + tx] = __float2half_rn(v);
    }
}

// ============================================================================
// Kernel 1: gather + build feats as single fp16   [C, 4H]
// ============================================================================
__device__ __forceinline__ void store_half4(float4 v, size_t elem_off) {
    unsigned short h0 = __half_as_ushort(__float2half_rn(v.x));
    unsigned short h1 = __half_as_ushort(__float2half_rn(v.y));
    unsigned short h2 = __half_as_ushort(__float2half_rn(v.z));
    unsigned short h3 = __half_as_ushort(__float2half_rn(v.w));
    uint2 p;
    p.x = (uint32_t)h0 | ((uint32_t)h1 << 16);
    p.y = (uint32_t)h2 | ((uint32_t)h3 << 16);
    *(uint2*)(g_fA + elem_off) = p;
}

__global__ void build_feats_kernel(const float* __restrict__ emb,
                                   const int* __restrict__ src_idx,
                                   const int* __restrict__ dst_idx) {
    const int c = blockIdx.x;
    const int h = threadIdx.x << 2;                 // 0..1020
    const int si = src_idx[c];
    const int di = dst_idx[c];

    const float4 s = *(const float4*)(emb + (size_t)si * HID + h);
    const float4 d = *(const float4*)(emb + (size_t)di * HID + h);

    float4 ad, pd;
    ad.x = fabsf(s.x - d.x); ad.y = fabsf(s.y - d.y);
    ad.z = fabsf(s.z - d.z); ad.w = fabsf(s.w - d.w);
    pd.x = s.x * d.x; pd.y = s.y * d.y; pd.z = s.z * d.z; pd.w = s.w * d.w;

    const size_t base = (size_t)c * K4;
    store_half4(s,  base + h);
    store_half4(d,  base + HID + h);
    store_half4(ad, base + 2 * HID + h);
    store_half4(pd, base + 3 * HID + h);
}

// ============================================================================
// Kernel 2: h = gelu(feats @ W1 + b1), single-product pure fp16 mma.sync.
// CTA tile 128x128, Kc=32, 4-stage cp.async pipe (16KB/stage, 64KB/CTA),
// 2 CTAs/SM. 8 warps as 4(M)x2(N); warp tile 32x64.
// Per k16 per warp: 4 LDSM.x4 (16 cyc) vs 8 HMMA (~32 cyc) -> MMA-bound.
// ============================================================================
#define BM          128
#define BN          128
#define BK          32
#define NSTAGE      4
#define STG_BYTES   16384    // A 8K | B 8K
#define OFF_A       0
#define OFF_B       8192
#define GEMM_SMEM   (NSTAGE * STG_BYTES)

__device__ __forceinline__ void load_stage(int t, int slot, int tid, int m0, int n0,
                                           uint32_t sb) {
    const int k0 = t * BK;
    const uint32_t st = sb + slot * STG_BYTES;
    #pragma unroll
    for (int i = 0; i < 2; ++i) {
        const int idx = i * 256 + tid;         // 0..511
        const int r = idx >> 2;                // row 0..127
        const int c = idx & 3;                 // 16B chunk 0..3
        const uint32_t d = st + r * 64 + ((c ^ ((r >> 1) & 3)) << 4);
        const size_t goA = (size_t)(m0 + r) * K4 + k0 + c * 8;
        const size_t goB = (size_t)(n0 + r) * K4 + k0 + c * 8;
        cpasync16(d + OFF_A, g_fA + goA);
        cpasync16(d + OFF_B, g_wF + goB);
    }
}

__global__ void __launch_bounds__(256, 2)
gemm1_mma_kernel(const float* __restrict__ b1) {
    extern __shared__ __align__(128) char smem[];
    const uint32_t sb = smem_u32(smem);
    const int tid  = threadIdx.x;
    const int lane = tid & 31;
    const int wrp  = tid >> 5;
    const int n0 = blockIdx.x * BN;      // x fastest: N tiles of one M block co-run
    const int m0 = blockIdx.y * BM;

    const int m_off = (wrp & 3) * 32;    // warp M origin
    const int n_off = (wrp >> 2) * 64;   // warp N origin

    const int l15 = lane & 15;
    const int lhf = lane >> 4;           // 0/1: 16B chunk within 16-col block

    uint32_t rAb[2], rBb[4];
    uint32_t rAs[2], rBs[4];
    #pragma unroll
    for (int mt = 0; mt < 2; ++mt) {
        const int r = m_off + mt * 16 + l15;
        rAb[mt] = (uint32_t)r * 64;
        rAs[mt] = (uint32_t)((r >> 1) & 3);
    }
    #pragma unroll
    for (int nt = 0; nt < 4; ++nt) {
        const int r = n_off + nt * 16 + l15;
        rBb[nt] = (uint32_t)r * 64;
        rBs[nt] = (uint32_t)((r >> 1) & 3);
    }

    float acc[2][8][4];
    #pragma unroll
    for (int mt = 0; mt < 2; ++mt)
        #pragma unroll
        for (int j = 0; j < 8; ++j)
            #pragma unroll
            for (int q = 0; q < 4; ++q) acc[mt][j][q] = 0.0f;

    load_stage(0, 0, tid, m0, n0, sb);
    asm volatile("cp.async.commit_group;" ::: "memory");
    load_stage(1, 1, tid, m0, n0, sb);
    asm volatile("cp.async.commit_group;" ::: "memory");
    load_stage(2, 2, tid, m0, n0, sb);
    asm volatile("cp.async.commit_group;" ::: "memory");

    const int NT = K4 / BK;   // 128
    for (int t = 0; t < NT; ++t) {
        const int slot = t & 3;
        asm volatile("cp.async.wait_group 2;" ::: "memory");
        __syncthreads();

        if (t + 3 < NT) load_stage(t + 3, (t + 3) & 3, tid, m0, n0, sb);
        asm volatile("cp.async.commit_group;" ::: "memory");

        const uint32_t st = sb + slot * STG_BYTES;
        #pragma unroll
        for (int kk = 0; kk < 2; ++kk) {
            const uint32_t ck = (uint32_t)(kk * 2 + lhf);
            uint32_t aF[2][4];
            #pragma unroll
            for (int mt = 0; mt < 2; ++mt) {
                const uint32_t ao = rAb[mt] + ((ck ^ rAs[mt]) << 4);
                ldsm4(aF[mt][0], aF[mt][1], aF[mt][2], aF[mt][3], st + OFF_A + ao);
            }
            uint32_t bF[8][2];
            #pragma unroll
            for (int nt = 0; nt < 4; ++nt) {
                const uint32_t bo = rBb[nt] + ((ck ^ rBs[nt]) << 4);
                uint32_t r0, r1, r2, r3;
                ldsm4(r0, r1, r2, r3, st + OFF_B + bo);
                bF[2 * nt][0] = r0; bF[2 * nt][1] = r2;
                bF[2 * nt + 1][0] = r1; bF[2 * nt + 1][1] = r3;
            }
            #pragma unroll
            for (int mt = 0; mt < 2; ++mt)
                #pragma unroll
                for (int j = 0; j < 8; ++j)
                    mma16816h(acc[mt][j], aF[mt], bF[j]);
        }
    }

    // epilogue: + bias, exact GELU, direct global stores (float2)
    const int mrow = m0 + m_off + (lane >> 2);
    const int col0 = n0 + n_off + 2 * (lane & 3);
    #pragma unroll
    for (int mt = 0; mt < 2; ++mt) {
        const int r = mrow + mt * 16;
        #pragma unroll
        for (int j = 0; j < 8; ++j) {
            const int c = col0 + j * 8;
            const float bb0 = __ldg(b1 + c);
            const float bb1 = __ldg(b1 + c + 1);
            float2 v0, v1;
            v0.x = gelu_exact(acc[mt][j][0] + bb0);
            v0.y = gelu_exact(acc[mt][j][1] + bb1);
            v1.x = gelu_exact(acc[mt][j][2] + bb0);
            v1.y = gelu_exact(acc[mt][j][3] + bb1);
            *(float2*)(g_h + (size_t)r * HID + c)       = v0;
            *(float2*)(g_h + (size_t)(r + 8) * HID + c) = v1;
        }
    }
}

// ============================================================================
// Kernel 3: logits = h @ W2 + b2 ; log-softmax ; NLL
// 4 candidates per warp sharing each Wt float4 read.
// ============================================================================
__global__ __launch_bounds__(256)
void head_kernel(const float* __restrict__ W2, const float* __restrict__ b2,
                 const int* __restrict__ labels, float* __restrict__ logits_out) {
    __shared__ float Wt[NREL][HID];   // 40 KB

    const int tid = threadIdx.x;
    for (int i = tid; i < NREL * HID; i += 256) {
        const int k = i / NREL;
        const int r = i - k * NREL;
        Wt[r][k] = W2[i];
    }
    __syncthreads();

    const int warp = tid >> 5;
    const int lane = tid & 31;
    const int c0 = blockIdx.x * 32 + warp * 4;

    const float* h0 = g_h + (size_t)(c0 + 0) * HID;
    const float* h1 = g_h + (size_t)(c0 + 1) * HID;
    const float* h2 = g_h + (size_t)(c0 + 2) * HID;
    const float* h3 = g_h + (size_t)(c0 + 3) * HID;

    float acc0[NREL], acc1[NREL], acc2[NREL], acc3[NREL];
    #pragma unroll
    for (int r = 0; r < NREL; ++r) { acc0[r] = 0.f; acc1[r] = 0.f; acc2[r] = 0.f; acc3[r] = 0.f; }

    #pragma unroll
    for (int i = 0; i < 8; ++i) {
        const int k = (i * 32 + lane) * 4;      // float4 index, coalesced
        const float4 a0 = *(const float4*)(h0 + k);
        const float4 a1 = *(const float4*)(h1 + k);
        const float4 a2 = *(const float4*)(h2 + k);
        const float4 a3 = *(const float4*)(h3 + k);
        #pragma unroll
        for (int r = 0; r < NREL; ++r) {
            const float4 w = *(const float4*)&Wt[r][k];   // broadcast, read ONCE
            acc0[r] += a0.x * w.x + a0.y * w.y + a0.z * w.z + a0.w * w.w;
            acc1[r] += a1.x * w.x + a1.y * w.y + a1.z * w.z + a1.w * w.w;
            acc2[r] += a2.x * w.x + a2.y * w.y + a2.z * w.z + a2.w * w.w;
            acc3[r] += a3.x * w.x + a3.y * w.y + a3.z * w.z + a3.w * w.w;
        }
    }

    #pragma unroll
    for (int r = 0; r < NREL; ++r) {
        #pragma unroll
        for (int off = 16; off > 0; off >>= 1) {
            acc0[r] += __shfl_down_sync(0xffffffffu, acc0[r], off);
            acc1[r] += __shfl_down_sync(0xffffffffu, acc1[r], off);
            acc2[r] += __shfl_down_sync(0xffffffffu, acc2[r], off);
            acc3[r] += __shfl_down_sync(0xffffffffu, acc3[r], off);
        }
    }

    if (lane == 0) {
        float* accs[4] = { acc0, acc1, acc2, acc3 };
        #pragma unroll
        for (int cc = 0; cc < 4; ++cc) {
            const int c = c0 + cc;
            float lg[NREL];
            float mx = -1e30f;
            #pragma unroll
            for (int r = 0; r < NREL; ++r) {
                lg[r] = accs[cc][r] + b2[r];
                mx = fmaxf(mx, lg[r]);
            }
            float s = 0.0f;
            #pragma unroll
            for (int r = 0; r < NREL; ++r) s += expf(lg[r] - mx);
            const float lse = logf(s) + mx;

            const int lbl = labels[c];
            g_loss[c] = lse - lg[lbl];

            float* dst = logits_out + (size_t)c * NREL;
            #pragma unroll
            for (int r = 0; r < NREL; ++r) dst[r] = lg[r];
        }
    }
}

// ============================================================================
// Kernel 4: loss = mean(g_loss)  -- single block, fixed-order tree
// ============================================================================
__global__ void reduce_loss_kernel(float* __restrict__ loss_out) {
    __shared__ float sm[1024];
    const int tid = threadIdx.x;
    float s = 0.0f;
    #pragma unroll
    for (int i = 0; i < 32; ++i) s += g_loss[tid + (i << 10)];
    sm[tid] = s;
    __syncthreads();
    for (int off = 512; off > 0; off >>= 1) {
        if (tid < off) sm[tid] += sm[tid + off];
        __syncthreads();
    }
    if (tid == 0) loss_out[0] = sm[0] * (1.0f / (float)C_CAND);
}

// ============================================================================
// launch
// ============================================================================
extern "C" void kernel_launch(void* const* d_in, const int* in_sizes, int n_in,
                              void* d_out, int out_size) {
    const float* emb    = (const float*)d_in[0];   // [100000, 1024]
    const int*   src    = (const int*)d_in[1];     // [32768]
    const int*   dst    = (const int*)d_in[2];     // [32768]
    const int*   labels = (const int*)d_in[3];     // [32768]
    const float* W1     = (const float*)d_in[4];   // [4096, 1024]
    const float* b1     = (const float*)d_in[5];   // [1024]
    const float* W2     = (const float*)d_in[6];   // [1024, 10]
    const float* b2     = (const float*)d_in[7];   // [10]

    float* out = (float*)d_out;
    float* logits_dst;
    float* loss_dst = nullptr;

    if (out_size >= C_CAND * NREL + 1) {
        loss_dst   = out;
        logits_dst = out + 1;
    } else if (out_size == C_CAND * NREL) {
        logits_dst = out;
    } else {
        void* p = nullptr;
        cudaGetSymbolAddress(&p, g_logits_sink);
        logits_dst = (float*)p;
        loss_dst   = out;
    }

    cudaFuncSetAttribute(gemm1_mma_kernel,
                         cudaFuncAttributeMaxDynamicSharedMemorySize, GEMM_SMEM);

    dim3 gw(K4 / 32, HID / 32);
    wsplit_kernel<<<gw, dim3(32, 8)>>>(W1);

    build_feats_kernel<<<C_CAND, 256>>>(emb, src, dst);

    dim3 gg(HID / BN, C_CAND / BM);    // (8, 256), x = N tile
    gemm1_mma_kernel<<<gg, 256, GEMM_SMEM>>>(b1);

    head_kernel<<<C_CAND / 32, 256>>>(W2, b2, labels, logits_dst);

    if (loss_dst) reduce_loss_kernel<<<1, 1024>>>(loss_dst);
}